// round 8
// baseline (speedup 1.0000x reference)
#include <cuda_runtime.h>
#include <cuda_bf16.h>
#include <math.h>
#include <stdint.h>

#define BB 8
#define SS 4096
#define NR (BB*SS)      // 32768 rows
#define EE 512
#define MF 256
#define SPLITK 8
#define NSTAGE 3
#define KCB 64                      // k elements (bf16) per chunk = 128B rows
#define STG_B 49152                 // bytes per stage: A 16KB + B 32KB
#define SMEM_B (NSTAGE*STG_B)       // 144KB

typedef __nv_bfloat16 bf16;
typedef __nv_bfloat162 bf162;

// ---------------- scratch (device globals; no allocation allowed) ----------
__device__ bf16  g_xnh [(size_t)NR*EE];
__device__ bf16  g_xnl [(size_t)NR*EE];
__device__ bf16  g_qb  [(size_t)NR*EE];
__device__ bf16  g_kb  [(size_t)NR*EE];
__device__ bf16  g_yb  [(size_t)NR*EE];
__device__ bf16  g_vtb [(size_t)NR*EE];    // [b][E][S]
__device__ bf16  g_qpb [(size_t)NR*MF];
__device__ bf16  g_kpb [(size_t)NR*MF];
__device__ bf16  g_kptb[(size_t)NR*MF];    // [b][M][S]
__device__ float g_v   [(size_t)NR*EE];
__device__ float g_t1  [(size_t)NR*EE];
__device__ float g_xdq[NR];
__device__ float g_xdk[NR];
__device__ float g_D  [NR];
__device__ float g_ks [BB*MF];
__device__ float g_kptvp[(size_t)SPLITK*BB*EE*MF];
__device__ bf16  g_kptvb[(size_t)BB*EE*MF];
__device__ bf16  g_qwb[EE*EE];
__device__ bf16  g_kwb[EE*EE];
__device__ bf16  g_pwb[EE*EE];
__device__ bf16  g_wb [MF*EE];
__device__ bf16  g_vwh[EE*EE];
__device__ bf16  g_vwl[EE*EE];

// =================== portable tensor-core helpers (sm_80+) =================
__device__ __forceinline__ void ldsm4(uint32_t* r, uint32_t addr){
    asm volatile("ldmatrix.sync.aligned.m8n8.x4.shared.b16 {%0,%1,%2,%3}, [%4];"
        : "=r"(r[0]), "=r"(r[1]), "=r"(r[2]), "=r"(r[3]) : "r"(addr));
}
__device__ __forceinline__ void mma16(float* d, const uint32_t* a, const uint32_t* b){
    asm volatile("mma.sync.aligned.m16n8k16.row.col.f32.bf16.bf16.f32 "
        "{%0,%1,%2,%3}, {%4,%5,%6,%7}, {%8,%9}, {%0,%1,%2,%3};"
        : "+f"(d[0]), "+f"(d[1]), "+f"(d[2]), "+f"(d[3])
        : "r"(a[0]), "r"(a[1]), "r"(a[2]), "r"(a[3]), "r"(b[0]), "r"(b[1]));
}
__device__ __forceinline__ void cpa16(uint32_t dst, const void* src){
    asm volatile("cp.async.cg.shared.global [%0], [%1], 16;"
                 :: "r"(dst), "l"(src) : "memory");
}
#define CP_COMMIT() asm volatile("cp.async.commit_group;" ::: "memory")
#define CP_WAIT1()  asm volatile("cp.async.wait_group 1;" ::: "memory")

// =================== bf16 mma.sync GEMM, tile 128x256 ======================
// C[r,c] = sum_k A[r,k]*W[c,k], bf16 K-major (row strides lda/ldw elements).
// 8 warps as 2m x 4n, warp tile 64x64, K chunks of 64, fp32 accum. 1 CTA/SM.
// MODE 0: +bias[c]            -> bf16 out   (q/k proj)
// MODE 1: expf(acc-xd[r])/16  -> bf16 out   (features)
// MODE 2: acc/(Dv[z,r]+eps)   -> bf16 out   (y)
// MODE 3: +bias[c]+addsrc     -> f32 out    (v main, final)
// MODE 4: plain               -> f32 out    (kptv partials / t1; split-K ok)
// MODE 5: +addsrc             -> f32 out    (t1 += xnl@vwh; addsrc may ==C)
template<int MODE>
__global__ __launch_bounds__(256, 1) void gemm_bf(
    const bf16* __restrict__ A, const bf16* __restrict__ W, void* __restrict__ Cv,
    int K, int lda, int ldw, int ncols,
    const float* __restrict__ bias, const float* __restrict__ xd,
    const float* __restrict__ Dv, const float* __restrict__ addsrc,
    size_t aB, size_t wB, size_t cB, int dB, int splitk)
{
    extern __shared__ char smc[];
    const uint32_t sb = (uint32_t)__cvta_generic_to_shared(smc);
    const int tid = threadIdx.x, lane = tid & 31, wid = tid >> 5;
    const int z = blockIdx.z;
    const bf16* Ab = A;
    const bf16* Wb = W;
    size_t cOff;
    if (MODE == 4 && splitk > 1) {
        int b = z / splitk, sk = z - b*splitk;
        Ab += b*aB + (size_t)sk*K;
        Wb += b*wB + (size_t)sk*K;
        cOff = (size_t)z*cB;
    } else {
        Ab += (size_t)z*aB; Wb += (size_t)z*wB; cOff = (size_t)z*cB;
    }
    const int rowBase = blockIdx.x*128, colBase = blockIdx.y*256;

    // fill mapping: threads 0..127 load A row (tid), all 256 load B row (tid)
    const bf16* gA = Ab + (size_t)(rowBase + (tid & 127))*lda;
    const bf16* gB = Wb + (size_t)(colBase + tid)*ldw;
    const uint32_t sArow = sb + (uint32_t)(tid & 127)*128u;
    const uint32_t sBrow = sb + 16384u + (uint32_t)tid*128u;
    const int fsw = tid & 7;
    const int nCh = K / KCB;

    #define LOAD_STAGE(i) do {                                            \
        if ((i) < nCh) {                                                  \
            const uint32_t stg = ((i) % NSTAGE)*STG_B;                    \
            const bf16* sA = gA + (size_t)(i)*KCB;                        \
            const bf16* sB = gB + (size_t)(i)*KCB;                        \
            if (tid < 128) {                                              \
                _Pragma("unroll")                                         \
                for (int j = 0; j < 8; j++)                               \
                    cpa16(sArow + stg + (uint32_t)((j ^ fsw) << 4), sA + 8*j); \
            }                                                             \
            _Pragma("unroll")                                             \
            for (int j = 0; j < 8; j++)                                   \
                cpa16(sBrow + stg + (uint32_t)((j ^ fsw) << 4), sB + 8*j);\
        }                                                                 \
        CP_COMMIT();                                                      \
    } while (0)

    LOAD_STAGE(0);
    LOAD_STAGE(1);

    const int wm = wid & 1, wn = wid >> 1;
    const int rq = lane >> 2;
    const int sw = lane & 7;
    const int lrow8 = (lane & 7) + ((lane >> 3) & 1) * 8;
    const int khalf = lane >> 4;
    uint32_t aOff[4], bOff[4];
    #pragma unroll
    for (int mi = 0; mi < 4; mi++)
        aOff[mi] = (uint32_t)(wm*64 + mi*16 + lrow8) * 128u;
    #pragma unroll
    for (int nb = 0; nb < 4; nb++)
        bOff[nb] = 16384u + (uint32_t)(wn*64 + nb*16 + lrow8) * 128u;

    float acc[4][8][4];
    #pragma unroll
    for (int mi = 0; mi < 4; mi++)
        #pragma unroll
        for (int ni = 0; ni < 8; ni++)
            #pragma unroll
            for (int t = 0; t < 4; t++) acc[mi][ni][t] = 0.f;

    for (int i = 0; i < nCh; i++) {
        CP_WAIT1();
        __syncthreads();
        const uint32_t sA = sb + (i % NSTAGE)*STG_B;
        #pragma unroll
        for (int ks = 0; ks < 4; ks++) {
            const uint32_t kq = (uint32_t)(((ks*2 + khalf) ^ sw) << 4);
            uint32_t af[4][4], bfr[8][2];
            #pragma unroll
            for (int mi = 0; mi < 4; mi++)
                ldsm4(af[mi], sA + aOff[mi] + kq);
            #pragma unroll
            for (int nb = 0; nb < 4; nb++) {
                uint32_t m[4];
                ldsm4(m, sA + bOff[nb] + kq);
                bfr[2*nb  ][0] = m[0]; bfr[2*nb+1][0] = m[1];
                bfr[2*nb  ][1] = m[2]; bfr[2*nb+1][1] = m[3];
            }
            #pragma unroll
            for (int mi = 0; mi < 4; mi++)
                #pragma unroll
                for (int ni = 0; ni < 8; ni++)
                    mma16(acc[mi][ni], af[mi], bfr[ni]);
        }
        LOAD_STAGE(i + NSTAGE - 1);
        __syncthreads();
    }

    // ---------------- epilogue ---------------------------------------------
    bf16*  Cb = (bf16*)Cv + cOff;
    float* Cf = (float*)Cv + cOff;
    const int c2 = (lane & 3)*2;
    #pragma unroll
    for (int mi = 0; mi < 4; mi++) {
        const int r0 = rowBase + wm*64 + mi*16 + rq;
        const int r1 = r0 + 8;
        float e0 = 0.f, e1 = 0.f, d0 = 1.f, d1 = 1.f;
        if (MODE == 1) { e0 = xd[r0]; e1 = xd[r1]; }
        if (MODE == 2) {
            d0 = 1.f/(Dv[(size_t)z*dB + r0] + 1e-8f);
            d1 = 1.f/(Dv[(size_t)z*dB + r1] + 1e-8f);
        }
        #pragma unroll
        for (int ni = 0; ni < 8; ni++) {
            const int cc = colBase + wn*64 + ni*8 + c2;
            float t0 = acc[mi][ni][0], t1v = acc[mi][ni][1];
            float t2 = acc[mi][ni][2], t3  = acc[mi][ni][3];
            if (MODE == 0) {
                float2 bv = *reinterpret_cast<const float2*>(bias + cc);
                t0 += bv.x; t1v += bv.y; t2 += bv.x; t3 += bv.y;
            } else if (MODE == 1) {
                t0 = expf(t0 - e0)*0.0625f; t1v = expf(t1v - e0)*0.0625f;
                t2 = expf(t2 - e1)*0.0625f; t3  = expf(t3  - e1)*0.0625f;
            } else if (MODE == 2) {
                t0 *= d0; t1v *= d0; t2 *= d1; t3 *= d1;
            } else if (MODE == 3) {
                float2 bv = *reinterpret_cast<const float2*>(bias + cc);
                float2 s0 = *reinterpret_cast<const float2*>(addsrc + (size_t)r0*ncols + cc);
                float2 s1 = *reinterpret_cast<const float2*>(addsrc + (size_t)r1*ncols + cc);
                t0 += bv.x + s0.x; t1v += bv.y + s0.y;
                t2 += bv.x + s1.x; t3  += bv.y + s1.y;
            } else if (MODE == 5) {
                float2 s0 = *reinterpret_cast<const float2*>(addsrc + (size_t)r0*ncols + cc);
                float2 s1 = *reinterpret_cast<const float2*>(addsrc + (size_t)r1*ncols + cc);
                t0 += s0.x; t1v += s0.y; t2 += s1.x; t3 += s1.y;
            }
            if (MODE <= 2) {
                *reinterpret_cast<bf162*>(Cb + (size_t)r0*ncols + cc) = __floats2bfloat162_rn(t0, t1v);
                *reinterpret_cast<bf162*>(Cb + (size_t)r1*ncols + cc) = __floats2bfloat162_rn(t2, t3);
            } else {
                *reinterpret_cast<float2*>(Cf + (size_t)r0*ncols + cc) = make_float2(t0, t1v);
                *reinterpret_cast<float2*>(Cf + (size_t)r1*ncols + cc) = make_float2(t2, t3);
            }
        }
    }
    #undef LOAD_STAGE
}

// ---------------- one fused weight-conversion kernel -----------------------
__global__ __launch_bounds__(256) void conv_all(
    const float* __restrict__ qw, const float* __restrict__ kw,
    const float* __restrict__ pw, const float* __restrict__ w,
    const float* __restrict__ vw,
    bf16* __restrict__ qwb, bf16* __restrict__ kwb, bf16* __restrict__ pwb,
    bf16* __restrict__ wb, bf16* __restrict__ vwh, bf16* __restrict__ vwl)
{
    int i = blockIdx.x*256 + threadIdx.x;
    const int N1 = EE*EE;           // 262144
    if (i < N1) {
        qwb[i] = __float2bfloat16_rn(qw[i]);
    } else if (i < 2*N1) {
        int j = i - N1; kwb[j] = __float2bfloat16_rn(kw[j]);
    } else if (i < 3*N1) {
        int j = i - 2*N1; pwb[j] = __float2bfloat16_rn(pw[j]);
    } else if (i < 3*N1 + MF*EE) {
        int j = i - 3*N1; wb[j] = __float2bfloat16_rn(w[j]);
    } else {
        int j = i - 3*N1 - MF*EE;
        float v = vw[j];
        bf16 hv = __float2bfloat16_rn(v);
        vwh[j] = hv;
        vwl[j] = __float2bfloat16_rn(v - __bfloat162float(hv));
    }
}

// ---------------- LayerNorm -> (hi, lo) bf16 -------------------------------
__global__ __launch_bounds__(128) void ln_kernel(
    const float* __restrict__ x, const float* __restrict__ gamma,
    const float* __restrict__ beta, bf16* __restrict__ xh, bf16* __restrict__ xl)
{
    int row = blockIdx.x;
    const float4* xr = reinterpret_cast<const float4*>(x + (size_t)row*EE);
    int t = threadIdx.x;
    float4 v = xr[t];
    float s  = v.x+v.y+v.z+v.w;
    float s2 = v.x*v.x+v.y*v.y+v.z*v.z+v.w*v.w;
    #pragma unroll
    for (int o=16;o>0;o>>=1){
        s  += __shfl_xor_sync(0xffffffffu, s,  o);
        s2 += __shfl_xor_sync(0xffffffffu, s2, o);
    }
    __shared__ float rs[4], rs2[4];
    int wid = t>>5, lane = t&31;
    if (lane==0){ rs[wid]=s; rs2[wid]=s2; }
    __syncthreads();
    s  = rs[0]+rs[1]+rs[2]+rs[3];
    s2 = rs2[0]+rs2[1]+rs2[2]+rs2[3];
    float mu  = s * (1.f/EE);
    float var = s2*(1.f/EE) - mu*mu;
    float inv = rsqrtf(var + 1e-5f);
    float4 g  = reinterpret_cast<const float4*>(gamma)[t];
    float4 bt = reinterpret_cast<const float4*>(beta)[t];
    float o[4];
    o[0] = (v.x-mu)*inv*g.x + bt.x;
    o[1] = (v.y-mu)*inv*g.y + bt.y;
    o[2] = (v.z-mu)*inv*g.z + bt.z;
    o[3] = (v.w-mu)*inv*g.w + bt.w;
    bf16 h[4]; float l[4];
    #pragma unroll
    for (int j=0;j<4;j++){ h[j]=__float2bfloat16_rn(o[j]); l[j]=o[j]-__bfloat162float(h[j]); }
    bf162* ph = reinterpret_cast<bf162*>(xh + (size_t)row*EE + t*4);
    bf162* pl = reinterpret_cast<bf162*>(xl + (size_t)row*EE + t*4);
    ph[0] = bf162(h[0], h[1]);  ph[1] = bf162(h[2], h[3]);
    pl[0] = __floats2bfloat162_rn(l[0], l[1]);
    pl[1] = __floats2bfloat162_rn(l[2], l[3]);
}

// ---------------- 0.5*||row||^2 of bf16 q,k --------------------------------
__device__ __forceinline__ float sumsq8(uint4 u){
    float s = 0.f;
    uint32_t a[4] = {u.x, u.y, u.z, u.w};
    #pragma unroll
    for (int j=0;j<4;j++){
        float2 f = __bfloat1622float2(*reinterpret_cast<bf162*>(&a[j]));
        s += f.x*f.x + f.y*f.y;
    }
    return s;
}
__global__ __launch_bounds__(256) void xd_kernel(
    const bf16* __restrict__ q, const bf16* __restrict__ k,
    float* __restrict__ xdq, float* __restrict__ xdk)
{
    int row  = blockIdx.x*8 + (threadIdx.x>>5);
    int lane = threadIdx.x&31;
    const uint4* qr = reinterpret_cast<const uint4*>(q + (size_t)row*EE);
    const uint4* kr = reinterpret_cast<const uint4*>(k + (size_t)row*EE);
    float sq=0.f, sk=0.f;
    #pragma unroll
    for (int j=0;j<2;j++){
        sq += sumsq8(qr[lane + j*32]);
        sk += sumsq8(kr[lane + j*32]);
    }
    #pragma unroll
    for (int o=16;o>0;o>>=1){
        sq += __shfl_xor_sync(0xffffffffu, sq, o);
        sk += __shfl_xor_sync(0xffffffffu, sk, o);
    }
    if (lane==0){ xdq[row]=0.5f*sq; xdk[row]=0.5f*sk; }
}

// ---------------- column sums of kp (bf16) per batch -----------------------
__global__ __launch_bounds__(256) void ksum_kernel(
    const bf16* __restrict__ kp, float* __restrict__ out)
{
    int b = blockIdx.x, m0 = blockIdx.y*64;
    int tx = threadIdx.x & 63, ty = threadIdx.x >> 6;
    const bf16* base = kp + (size_t)b*SS*MF + m0 + tx;
    float s=0.f;
    for (int srow=ty; srow<SS; srow+=4) s += __bfloat162float(base[(size_t)srow*MF]);
    __shared__ float red[4][64];
    red[ty][tx]=s;
    __syncthreads();
    if (ty==0) out[b*MF+m0+tx] = red[0][tx]+red[1][tx]+red[2][tx]+red[3][tx];
}

// ---------------- batched 2D transpose with dtype convert ------------------
__device__ __forceinline__ float ldf(const float* p){ return *p; }
__device__ __forceinline__ float ldf(const bf16* p){ return __bfloat162float(*p); }
__device__ __forceinline__ void stf(float* p, float v){ *p = v; }
__device__ __forceinline__ void stf(bf16* p, float v){ *p = __float2bfloat16_rn(v); }

template<typename TI, typename TO>
__global__ __launch_bounds__(256) void transpose_t(
    const TI* __restrict__ in, TO* __restrict__ out, int R, int Cc)
{
    __shared__ float t[32][33];
    int z = blockIdx.z;
    in  += (size_t)z*R*Cc;
    out += (size_t)z*R*Cc;
    int tx = threadIdx.x & 31, ty = threadIdx.x >> 5;
    int x  = blockIdx.x*32 + tx;
    int y0 = blockIdx.y*32;
    #pragma unroll
    for (int j=0;j<4;j++)
        t[ty + j*8][tx] = ldf(in + (size_t)(y0 + ty + j*8)*Cc + x);
    __syncthreads();
    int xo = y0 + tx;
    int c0 = blockIdx.x*32;
    #pragma unroll
    for (int j=0;j<4;j++)
        stf(out + (size_t)(c0 + ty + j*8)*R + xo, t[tx][ty + j*8]);
}

// ---------------- reduce split-K partials -> bf16 --------------------------
__global__ __launch_bounds__(256) void reduce_kptv(
    const float* __restrict__ p, bf16* __restrict__ o)
{
    const size_t EM = (size_t)EE*MF;
    size_t i = (size_t)blockIdx.x*256 + threadIdx.x;
    int b = blockIdx.y;
    const float* pb = p + (size_t)b*SPLITK*EM + i;
    float s = 0.f;
    #pragma unroll
    for (int sk=0; sk<SPLITK; sk++) s += pb[(size_t)sk*EM];
    o[(size_t)b*EM + i] = __float2bfloat16_rn(s);
}

// ---------------- D[r] = qp[r,:] . ksum[b,:] -------------------------------
__global__ __launch_bounds__(256) void d_kernel(
    const bf16* __restrict__ qp, const float* __restrict__ ks,
    float* __restrict__ D)
{
    int row  = blockIdx.x*8 + (threadIdx.x>>5);
    int lane = threadIdx.x&31;
    int b = row >> 12;
    uint4 u = *reinterpret_cast<const uint4*>(qp + (size_t)row*MF + lane*8);
    float4 k0 = *reinterpret_cast<const float4*>(ks + b*MF + lane*8);
    float4 k1 = *reinterpret_cast<const float4*>(ks + b*MF + lane*8 + 4);
    uint32_t a[4] = {u.x, u.y, u.z, u.w};
    float kk[8] = {k0.x,k0.y,k0.z,k0.w,k1.x,k1.y,k1.z,k1.w};
    float s=0.f;
    #pragma unroll
    for (int j=0;j<4;j++){
        float2 f = __bfloat1622float2(*reinterpret_cast<bf162*>(&a[j]));
        s += f.x*kk[2*j] + f.y*kk[2*j+1];
    }
    #pragma unroll
    for (int o=16;o>0;o>>=1) s += __shfl_xor_sync(0xffffffffu, s, o);
    if (lane==0) D[row]=s;
}

// ---------------- launch ---------------------------------------------------
extern "C" void kernel_launch(void* const* d_in, const int* in_sizes, int n_in,
                              void* d_out, int out_size)
{
    const float* x     = (const float*)d_in[0];
    const float* qw    = (const float*)d_in[1];
    const float* qb    = (const float*)d_in[2];
    const float* kw    = (const float*)d_in[3];
    const float* kb    = (const float*)d_in[4];
    const float* vw    = (const float*)d_in[5];
    const float* vb    = (const float*)d_in[6];
    const float* pw    = (const float*)d_in[7];
    const float* pb    = (const float*)d_in[8];
    const float* gamma = (const float*)d_in[9];
    const float* beta  = (const float*)d_in[10];
    const float* w     = (const float*)d_in[11];
    float* out = (float*)d_out;

    bf16 *xnh,*xnl,*qbf,*kbf,*ybf,*vtb,*qpb,*kpb,*kptb,*kptvb;
    bf16 *qwb,*kwb,*pwb,*wb,*vwh,*vwl;
    float *v,*t1,*xdq,*xdk,*D,*ks,*kptvp;
    cudaGetSymbolAddress((void**)&xnh,  g_xnh);
    cudaGetSymbolAddress((void**)&xnl,  g_xnl);
    cudaGetSymbolAddress((void**)&qbf,  g_qb);
    cudaGetSymbolAddress((void**)&kbf,  g_kb);
    cudaGetSymbolAddress((void**)&ybf,  g_yb);
    cudaGetSymbolAddress((void**)&vtb,  g_vtb);
    cudaGetSymbolAddress((void**)&qpb,  g_qpb);
    cudaGetSymbolAddress((void**)&kpb,  g_kpb);
    cudaGetSymbolAddress((void**)&kptb, g_kptb);
    cudaGetSymbolAddress((void**)&kptvb,g_kptvb);
    cudaGetSymbolAddress((void**)&qwb,  g_qwb);
    cudaGetSymbolAddress((void**)&kwb,  g_kwb);
    cudaGetSymbolAddress((void**)&pwb,  g_pwb);
    cudaGetSymbolAddress((void**)&wb,   g_wb);
    cudaGetSymbolAddress((void**)&vwh,  g_vwh);
    cudaGetSymbolAddress((void**)&vwl,  g_vwl);
    cudaGetSymbolAddress((void**)&v,    g_v);
    cudaGetSymbolAddress((void**)&t1,   g_t1);
    cudaGetSymbolAddress((void**)&xdq,  g_xdq);
    cudaGetSymbolAddress((void**)&xdk,  g_xdk);
    cudaGetSymbolAddress((void**)&D,    g_D);
    cudaGetSymbolAddress((void**)&ks,   g_ks);
    cudaGetSymbolAddress((void**)&kptvp,g_kptvp);

    cudaFuncSetAttribute(gemm_bf<0>, cudaFuncAttributeMaxDynamicSharedMemorySize, SMEM_B);
    cudaFuncSetAttribute(gemm_bf<1>, cudaFuncAttributeMaxDynamicSharedMemorySize, SMEM_B);
    cudaFuncSetAttribute(gemm_bf<2>, cudaFuncAttributeMaxDynamicSharedMemorySize, SMEM_B);
    cudaFuncSetAttribute(gemm_bf<3>, cudaFuncAttributeMaxDynamicSharedMemorySize, SMEM_B);
    cudaFuncSetAttribute(gemm_bf<4>, cudaFuncAttributeMaxDynamicSharedMemorySize, SMEM_B);
    cudaFuncSetAttribute(gemm_bf<5>, cudaFuncAttributeMaxDynamicSharedMemorySize, SMEM_B);

    dim3 blk(256);

    // 1) weight conversions (single launch)
    {
        int total = 3*EE*EE + MF*EE + EE*EE;
        conv_all<<<(total+255)/256,blk>>>(qw, kw, pw, w, vw,
                                          qwb, kwb, pwb, wb, vwh, vwl);
    }

    // 2) LayerNorm -> (xnh, xnl)
    ln_kernel<<<NR,128>>>(x, gamma, beta, xnh, xnl);

    // 3) q/k projections (bf16 out), tile 128x256
    dim3 gqkv(NR/128, EE/256, 1);
    gemm_bf<0><<<gqkv,blk,SMEM_B>>>(xnh, qwb, qbf, EE, EE, EE, EE, qb, nullptr, nullptr, nullptr, 0,0,0,0,1);
    gemm_bf<0><<<gqkv,blk,SMEM_B>>>(xnh, kwb, kbf, EE, EE, EE, EE, kb, nullptr, nullptr, nullptr, 0,0,0,0,1);

    // 4) v via split-bf16: t1 = xnh@vwl; t1 += xnl@vwh; v = xnh@vwh + vb + t1
    gemm_bf<4><<<gqkv,blk,SMEM_B>>>(xnh, vwl, t1, EE, EE, EE, EE, nullptr, nullptr, nullptr, nullptr, 0,0,0,0,1);
    gemm_bf<5><<<gqkv,blk,SMEM_B>>>(xnl, vwh, t1, EE, EE, EE, EE, nullptr, nullptr, nullptr, t1, 0,0,0,0,1);
    gemm_bf<3><<<gqkv,blk,SMEM_B>>>(xnh, vwh, v,  EE, EE, EE, EE, vb, nullptr, nullptr, t1, 0,0,0,0,1);

    // 5) row half-norms from bf16 q,k
    xd_kernel<<<NR/8,256>>>(qbf, kbf, xdq, xdk);

    // 6) features (exp epilogue, bf16 out), N=256 -> grid y=1
    dim3 gqp(NR/128, 1, 1);
    gemm_bf<1><<<gqp,blk,SMEM_B>>>(qbf, wb, qpb, EE, EE, EE, MF, nullptr, xdq, nullptr, nullptr, 0,0,0,0,1);
    gemm_bf<1><<<gqp,blk,SMEM_B>>>(kbf, wb, kpb, EE, EE, EE, MF, nullptr, xdk, nullptr, nullptr, 0,0,0,0,1);

    // 7) ksum[b,m]
    ksum_kernel<<<dim3(BB, MF/64),blk>>>(kpb, ks);

    // 8) transposes: vtb[b][E][S] (f32->bf16), kptb[b][M][S] (bf16->bf16)
    transpose_t<float,bf16><<<dim3(EE/32, SS/32, BB),blk>>>(v,   vtb,  SS, EE);
    transpose_t<bf16,bf16> <<<dim3(MF/32, SS/32, BB),blk>>>(kpb, kptb, SS, MF);

    // 9) kptv split-K partials (f32), reduce -> bf16
    gemm_bf<4><<<dim3(EE/128, 1, BB*SPLITK),blk,SMEM_B>>>(
        vtb, kptb, kptvp, SS/SPLITK, SS, SS, MF, nullptr, nullptr, nullptr, nullptr,
        (size_t)EE*SS, (size_t)MF*SS, (size_t)EE*MF, 0, SPLITK);
    reduce_kptv<<<dim3((EE*MF)/256, BB),blk>>>(kptvp, kptvb);

    // 10) D[r]
    d_kernel<<<NR/8,256>>>(qpb, ks, D);

    // 11) y[b,s,e] = (qp @ kptv^T)/(D+eps), bf16 out
    gemm_bf<2><<<dim3(SS/128, EE/256, BB),blk,SMEM_B>>>(
        qpb, kptvb, ybf, MF, MF, MF, EE, nullptr, nullptr, D, nullptr,
        (size_t)SS*MF, (size_t)EE*MF, (size_t)SS*EE, SS, 1);

    // 12) out = v + y @ pw^T + pb   (f32 out)
    gemm_bf<3><<<gqkv,blk,SMEM_B>>>(ybf, pwb, out, EE, EE, EE, EE, pb, nullptr, nullptr, v, 0,0,0,0,1);
}

// round 9
// speedup vs baseline: 1.0841x; 1.0841x over previous
#include <cuda_runtime.h>
#include <cuda_bf16.h>
#include <math.h>
#include <stdint.h>

#define BB 8
#define SS 4096
#define NR (BB*SS)      // 32768 rows
#define EE 512
#define MF 256
#define SPLITK 8
#define NSTAGE 3
#define KCB 64                      // k elements (bf16) per chunk = 128B rows
#define STG_B 32768                 // bytes per stage: A 16KB + B 16KB
#define SMEM_B (NSTAGE*STG_B)       // 96KB

typedef __nv_bfloat16 bf16;
typedef __nv_bfloat162 bf162;

// ---------------- scratch (device globals; no allocation allowed) ----------
__device__ bf16  g_xhl [(size_t)NR*2*EE];  // [row][0:512]=hi, [512:1024]=lo
__device__ bf16  g_qb  [(size_t)NR*EE];
__device__ bf16  g_kb  [(size_t)NR*EE];
__device__ bf16  g_yb  [(size_t)NR*EE];
__device__ bf16  g_vtb [(size_t)NR*EE];    // [b][E][S]
__device__ bf16  g_qpb [(size_t)NR*MF];
__device__ bf16  g_kpb [(size_t)NR*MF];
__device__ bf16  g_kptb[(size_t)NR*MF];    // [b][M][S]
__device__ float g_v   [(size_t)NR*EE];
__device__ float g_t1  [(size_t)NR*EE];
__device__ float g_xdq[NR];
__device__ float g_xdk[NR];
__device__ float g_D  [NR];
__device__ float g_ks [BB*MF];
__device__ float g_kptvp[(size_t)SPLITK*BB*EE*MF];
__device__ bf16  g_kptvb[(size_t)BB*EE*MF];
__device__ bf16  g_qwb[EE*EE];
__device__ bf16  g_kwb[EE*EE];
__device__ bf16  g_pwb[EE*EE];
__device__ bf16  g_wb [MF*EE];
__device__ bf16  g_vwh[EE*EE];
__device__ bf16  g_vwlh[EE*2*EE];          // [col][0:512]=vwl, [512:1024]=vwh

// =================== portable tensor-core helpers (sm_80+) =================
__device__ __forceinline__ void ldsm4(uint32_t* r, uint32_t addr){
    asm volatile("ldmatrix.sync.aligned.m8n8.x4.shared.b16 {%0,%1,%2,%3}, [%4];"
        : "=r"(r[0]), "=r"(r[1]), "=r"(r[2]), "=r"(r[3]) : "r"(addr));
}
__device__ __forceinline__ void mma16(float* d, const uint32_t* a, const uint32_t* b){
    asm volatile("mma.sync.aligned.m16n8k16.row.col.f32.bf16.bf16.f32 "
        "{%0,%1,%2,%3}, {%4,%5,%6,%7}, {%8,%9}, {%0,%1,%2,%3};"
        : "+f"(d[0]), "+f"(d[1]), "+f"(d[2]), "+f"(d[3])
        : "r"(a[0]), "r"(a[1]), "r"(a[2]), "r"(a[3]), "r"(b[0]), "r"(b[1]));
}
__device__ __forceinline__ void cpa16(uint32_t dst, const void* src){
    asm volatile("cp.async.cg.shared.global [%0], [%1], 16;"
                 :: "r"(dst), "l"(src) : "memory");
}
#define CP_COMMIT() asm volatile("cp.async.commit_group;" ::: "memory")
#define CP_WAIT1()  asm volatile("cp.async.wait_group 1;" ::: "memory")

// =================== bf16 mma.sync GEMM, tile 128x128, 4 warps =============
// C[r,c] = sum_k A[r,k]*W[c,k], bf16 K-major (row strides lda/ldw elements).
// 4 warps as 2m x 2n, warp tile 64x64, K chunks of 64, fp32 accum. 2 CTA/SM.
// MODE 0: +bias[c]            -> bf16 out   (q/k proj)
// MODE 1: expf(acc-xd[r])/16  -> bf16 out   (features)
// MODE 2: acc/(Dv[z,r]+eps)   -> bf16 out   (y)
// MODE 3: +bias[c]+addsrc     -> f32 out    (v main, final)
// MODE 4: plain               -> f32 out    (kptv partials / t1; split-K ok)
template<int MODE>
__global__ __launch_bounds__(128, 2) void gemm_bf(
    const bf16* __restrict__ A, const bf16* __restrict__ W, void* __restrict__ Cv,
    int K, int lda, int ldw, int ncols,
    const float* __restrict__ bias, const float* __restrict__ xd,
    const float* __restrict__ Dv, const float* __restrict__ addsrc,
    size_t aB, size_t wB, size_t cB, int dB, int splitk)
{
    extern __shared__ char smc[];
    const uint32_t sb = (uint32_t)__cvta_generic_to_shared(smc);
    const int tid = threadIdx.x, lane = tid & 31, wid = tid >> 5;
    const int z = blockIdx.z;
    const bf16* Ab = A;
    const bf16* Wb = W;
    size_t cOff;
    if (MODE == 4 && splitk > 1) {
        int b = z / splitk, sk = z - b*splitk;
        Ab += b*aB + (size_t)sk*K;
        Wb += b*wB + (size_t)sk*K;
        cOff = (size_t)z*cB;
    } else {
        Ab += (size_t)z*aB; Wb += (size_t)z*wB; cOff = (size_t)z*cB;
    }
    const int rowBase = blockIdx.x*128, colBase = blockIdx.y*128;

    // fill mapping: thread t loads A row t and B row t (8 cpa16 each)
    const bf16* gA = Ab + (size_t)(rowBase + tid)*lda;
    const bf16* gB = Wb + (size_t)(colBase + tid)*ldw;
    const uint32_t sArow = sb + (uint32_t)tid*128u;
    const uint32_t sBrow = sb + 16384u + (uint32_t)tid*128u;
    const int fsw = tid & 7;
    const int nCh = K / KCB;

    #define LOAD_STAGE(i) do {                                            \
        if ((i) < nCh) {                                                  \
            const uint32_t stg = ((i) % NSTAGE)*STG_B;                    \
            const bf16* pA = gA + (size_t)(i)*KCB;                        \
            const bf16* pB = gB + (size_t)(i)*KCB;                        \
            _Pragma("unroll")                                             \
            for (int j = 0; j < 8; j++) {                                 \
                cpa16(sArow + stg + (uint32_t)((j ^ fsw) << 4), pA + 8*j);\
                cpa16(sBrow + stg + (uint32_t)((j ^ fsw) << 4), pB + 8*j);\
            }                                                             \
        }                                                                 \
        CP_COMMIT();                                                      \
    } while (0)

    LOAD_STAGE(0);
    LOAD_STAGE(1);

    const int wm = wid & 1, wn = wid >> 1;
    const int rq = lane >> 2;
    const int sw = lane & 7;
    const int lrow8 = (lane & 7) + ((lane >> 3) & 1) * 8;
    const int khalf = lane >> 4;
    uint32_t aOff[4], bOff[4];
    #pragma unroll
    for (int mi = 0; mi < 4; mi++)
        aOff[mi] = (uint32_t)(wm*64 + mi*16 + lrow8) * 128u;
    #pragma unroll
    for (int nb = 0; nb < 4; nb++)
        bOff[nb] = 16384u + (uint32_t)(wn*64 + nb*16 + lrow8) * 128u;

    float acc[4][8][4];
    #pragma unroll
    for (int mi = 0; mi < 4; mi++)
        #pragma unroll
        for (int ni = 0; ni < 8; ni++)
            #pragma unroll
            for (int t = 0; t < 4; t++) acc[mi][ni][t] = 0.f;

    for (int i = 0; i < nCh; i++) {
        CP_WAIT1();
        __syncthreads();
        const uint32_t sA = sb + (i % NSTAGE)*STG_B;
        #pragma unroll
        for (int ks = 0; ks < 4; ks++) {
            const uint32_t kq = (uint32_t)(((ks*2 + khalf) ^ sw) << 4);
            uint32_t af[4][4], bfr[8][2];
            #pragma unroll
            for (int mi = 0; mi < 4; mi++)
                ldsm4(af[mi], sA + aOff[mi] + kq);
            #pragma unroll
            for (int nb = 0; nb < 4; nb++) {
                uint32_t m[4];
                ldsm4(m, sA + bOff[nb] + kq);
                bfr[2*nb  ][0] = m[0]; bfr[2*nb+1][0] = m[1];
                bfr[2*nb  ][1] = m[2]; bfr[2*nb+1][1] = m[3];
            }
            #pragma unroll
            for (int mi = 0; mi < 4; mi++)
                #pragma unroll
                for (int ni = 0; ni < 8; ni++)
                    mma16(acc[mi][ni], af[mi], bfr[ni]);
        }
        LOAD_STAGE(i + NSTAGE - 1);
    }

    // ---------------- epilogue ---------------------------------------------
    bf16*  Cb = (bf16*)Cv + cOff;
    float* Cf = (float*)Cv + cOff;
    const int c2 = (lane & 3)*2;
    #pragma unroll
    for (int mi = 0; mi < 4; mi++) {
        const int r0 = rowBase + wm*64 + mi*16 + rq;
        const int r1 = r0 + 8;
        float e0 = 0.f, e1 = 0.f, d0 = 1.f, d1 = 1.f;
        if (MODE == 1) { e0 = xd[r0]; e1 = xd[r1]; }
        if (MODE == 2) {
            d0 = 1.f/(Dv[(size_t)z*dB + r0] + 1e-8f);
            d1 = 1.f/(Dv[(size_t)z*dB + r1] + 1e-8f);
        }
        #pragma unroll
        for (int ni = 0; ni < 8; ni++) {
            const int cc = colBase + wn*64 + ni*8 + c2;
            float t0 = acc[mi][ni][0], t1v = acc[mi][ni][1];
            float t2 = acc[mi][ni][2], t3  = acc[mi][ni][3];
            if (MODE == 0) {
                float2 bv = *reinterpret_cast<const float2*>(bias + cc);
                t0 += bv.x; t1v += bv.y; t2 += bv.x; t3 += bv.y;
            } else if (MODE == 1) {
                t0 = expf(t0 - e0)*0.0625f; t1v = expf(t1v - e0)*0.0625f;
                t2 = expf(t2 - e1)*0.0625f; t3  = expf(t3  - e1)*0.0625f;
            } else if (MODE == 2) {
                t0 *= d0; t1v *= d0; t2 *= d1; t3 *= d1;
            } else if (MODE == 3) {
                float2 bv = *reinterpret_cast<const float2*>(bias + cc);
                float2 s0 = *reinterpret_cast<const float2*>(addsrc + (size_t)r0*ncols + cc);
                float2 s1 = *reinterpret_cast<const float2*>(addsrc + (size_t)r1*ncols + cc);
                t0 += bv.x + s0.x; t1v += bv.y + s0.y;
                t2 += bv.x + s1.x; t3  += bv.y + s1.y;
            }
            if (MODE <= 2) {
                *reinterpret_cast<bf162*>(Cb + (size_t)r0*ncols + cc) = __floats2bfloat162_rn(t0, t1v);
                *reinterpret_cast<bf162*>(Cb + (size_t)r1*ncols + cc) = __floats2bfloat162_rn(t2, t3);
            } else {
                *reinterpret_cast<float2*>(Cf + (size_t)r0*ncols + cc) = make_float2(t0, t1v);
                *reinterpret_cast<float2*>(Cf + (size_t)r1*ncols + cc) = make_float2(t2, t3);
            }
        }
    }
    #undef LOAD_STAGE
}

// ---------------- one fused weight-conversion kernel -----------------------
__global__ __launch_bounds__(256) void conv_all(
    const float* __restrict__ qw, const float* __restrict__ kw,
    const float* __restrict__ pw, const float* __restrict__ w,
    const float* __restrict__ vw,
    bf16* __restrict__ qwb, bf16* __restrict__ kwb, bf16* __restrict__ pwb,
    bf16* __restrict__ wb, bf16* __restrict__ vwh, bf16* __restrict__ vwlh)
{
    int i = blockIdx.x*256 + threadIdx.x;
    const int N1 = EE*EE;           // 262144
    if (i < N1) {
        qwb[i] = __float2bfloat16_rn(qw[i]);
    } else if (i < 2*N1) {
        int j = i - N1; kwb[j] = __float2bfloat16_rn(kw[j]);
    } else if (i < 3*N1) {
        int j = i - 2*N1; pwb[j] = __float2bfloat16_rn(pw[j]);
    } else if (i < 3*N1 + MF*EE) {
        int j = i - 3*N1; wb[j] = __float2bfloat16_rn(w[j]);
    } else {
        int j = i - 3*N1 - MF*EE;
        int row = j >> 9, col = j & 511;
        float v = vw[j];
        bf16 hv = __float2bfloat16_rn(v);
        bf16 lv = __float2bfloat16_rn(v - __bfloat162float(hv));
        vwh[j] = hv;
        vwlh[(size_t)row*1024 + col]       = lv;   // pairs with xnh
        vwlh[(size_t)row*1024 + 512 + col] = hv;   // pairs with xnl
    }
}

// ---------------- LayerNorm -> interleaved (hi, lo) bf16 -------------------
__global__ __launch_bounds__(128) void ln_kernel(
    const float* __restrict__ x, const float* __restrict__ gamma,
    const float* __restrict__ beta, bf16* __restrict__ xhl)
{
    int row = blockIdx.x;
    const float4* xr = reinterpret_cast<const float4*>(x + (size_t)row*EE);
    int t = threadIdx.x;
    float4 v = xr[t];
    float s  = v.x+v.y+v.z+v.w;
    float s2 = v.x*v.x+v.y*v.y+v.z*v.z+v.w*v.w;
    #pragma unroll
    for (int o=16;o>0;o>>=1){
        s  += __shfl_xor_sync(0xffffffffu, s,  o);
        s2 += __shfl_xor_sync(0xffffffffu, s2, o);
    }
    __shared__ float rs[4], rs2[4];
    int wid = t>>5, lane = t&31;
    if (lane==0){ rs[wid]=s; rs2[wid]=s2; }
    __syncthreads();
    s  = rs[0]+rs[1]+rs[2]+rs[3];
    s2 = rs2[0]+rs2[1]+rs2[2]+rs2[3];
    float mu  = s * (1.f/EE);
    float var = s2*(1.f/EE) - mu*mu;
    float inv = rsqrtf(var + 1e-5f);
    float4 g  = reinterpret_cast<const float4*>(gamma)[t];
    float4 bt = reinterpret_cast<const float4*>(beta)[t];
    float o[4];
    o[0] = (v.x-mu)*inv*g.x + bt.x;
    o[1] = (v.y-mu)*inv*g.y + bt.y;
    o[2] = (v.z-mu)*inv*g.z + bt.z;
    o[3] = (v.w-mu)*inv*g.w + bt.w;
    bf16 h[4]; float l[4];
    #pragma unroll
    for (int j=0;j<4;j++){ h[j]=__float2bfloat16_rn(o[j]); l[j]=o[j]-__bfloat162float(h[j]); }
    bf162* ph = reinterpret_cast<bf162*>(xhl + (size_t)row*1024 + t*4);
    bf162* pl = reinterpret_cast<bf162*>(xhl + (size_t)row*1024 + 512 + t*4);
    ph[0] = bf162(h[0], h[1]);  ph[1] = bf162(h[2], h[3]);
    pl[0] = __floats2bfloat162_rn(l[0], l[1]);
    pl[1] = __floats2bfloat162_rn(l[2], l[3]);
}

// ---------------- 0.5*||row||^2 of bf16 q,k --------------------------------
__device__ __forceinline__ float sumsq8(uint4 u){
    float s = 0.f;
    uint32_t a[4] = {u.x, u.y, u.z, u.w};
    #pragma unroll
    for (int j=0;j<4;j++){
        float2 f = __bfloat1622float2(*reinterpret_cast<bf162*>(&a[j]));
        s += f.x*f.x + f.y*f.y;
    }
    return s;
}
__global__ __launch_bounds__(256) void xd_kernel(
    const bf16* __restrict__ q, const bf16* __restrict__ k,
    float* __restrict__ xdq, float* __restrict__ xdk)
{
    int row  = blockIdx.x*8 + (threadIdx.x>>5);
    int lane = threadIdx.x&31;
    const uint4* qr = reinterpret_cast<const uint4*>(q + (size_t)row*EE);
    const uint4* kr = reinterpret_cast<const uint4*>(k + (size_t)row*EE);
    float sq=0.f, sk=0.f;
    #pragma unroll
    for (int j=0;j<2;j++){
        sq += sumsq8(qr[lane + j*32]);
        sk += sumsq8(kr[lane + j*32]);
    }
    #pragma unroll
    for (int o=16;o>0;o>>=1){
        sq += __shfl_xor_sync(0xffffffffu, sq, o);
        sk += __shfl_xor_sync(0xffffffffu, sk, o);
    }
    if (lane==0){ xdq[row]=0.5f*sq; xdk[row]=0.5f*sk; }
}

// ---------------- column sums of kp (bf16) per batch -----------------------
__global__ __launch_bounds__(256) void ksum_kernel(
    const bf16* __restrict__ kp, float* __restrict__ out)
{
    int b = blockIdx.x, m0 = blockIdx.y*64;
    int tx = threadIdx.x & 63, ty = threadIdx.x >> 6;
    const bf16* base = kp + (size_t)b*SS*MF + m0 + tx;
    float s=0.f;
    for (int srow=ty; srow<SS; srow+=4) s += __bfloat162float(base[(size_t)srow*MF]);
    __shared__ float red[4][64];
    red[ty][tx]=s;
    __syncthreads();
    if (ty==0) out[b*MF+m0+tx] = red[0][tx]+red[1][tx]+red[2][tx]+red[3][tx];
}

// ---------------- batched 2D transpose with dtype convert ------------------
__device__ __forceinline__ float ldf(const float* p){ return *p; }
__device__ __forceinline__ float ldf(const bf16* p){ return __bfloat162float(*p); }
__device__ __forceinline__ void stf(float* p, float v){ *p = v; }
__device__ __forceinline__ void stf(bf16* p, float v){ *p = __float2bfloat16_rn(v); }

template<typename TI, typename TO>
__global__ __launch_bounds__(256) void transpose_t(
    const TI* __restrict__ in, TO* __restrict__ out, int R, int Cc)
{
    __shared__ float t[32][33];
    int z = blockIdx.z;
    in  += (size_t)z*R*Cc;
    out += (size_t)z*R*Cc;
    int tx = threadIdx.x & 31, ty = threadIdx.x >> 5;
    int x  = blockIdx.x*32 + tx;
    int y0 = blockIdx.y*32;
    #pragma unroll
    for (int j=0;j<4;j++)
        t[ty + j*8][tx] = ldf(in + (size_t)(y0 + ty + j*8)*Cc + x);
    __syncthreads();
    int xo = y0 + tx;
    int c0 = blockIdx.x*32;
    #pragma unroll
    for (int j=0;j<4;j++)
        stf(out + (size_t)(c0 + ty + j*8)*R + xo, t[tx][ty + j*8]);
}

// ---------------- reduce split-K partials -> bf16 --------------------------
__global__ __launch_bounds__(256) void reduce_kptv(
    const float* __restrict__ p, bf16* __restrict__ o)
{
    const size_t EM = (size_t)EE*MF;
    size_t i = (size_t)blockIdx.x*256 + threadIdx.x;
    int b = blockIdx.y;
    const float* pb = p + (size_t)b*SPLITK*EM + i;
    float s = 0.f;
    #pragma unroll
    for (int sk=0; sk<SPLITK; sk++) s += pb[(size_t)sk*EM];
    o[(size_t)b*EM + i] = __float2bfloat16_rn(s);
}

// ---------------- D[r] = qp[r,:] . ksum[b,:] -------------------------------
__global__ __launch_bounds__(256) void d_kernel(
    const bf16* __restrict__ qp, const float* __restrict__ ks,
    float* __restrict__ D)
{
    int row  = blockIdx.x*8 + (threadIdx.x>>5);
    int lane = threadIdx.x&31;
    int b = row >> 12;
    uint4 u = *reinterpret_cast<const uint4*>(qp + (size_t)row*MF + lane*8);
    float4 k0 = *reinterpret_cast<const float4*>(ks + b*MF + lane*8);
    float4 k1 = *reinterpret_cast<const float4*>(ks + b*MF + lane*8 + 4);
    uint32_t a[4] = {u.x, u.y, u.z, u.w};
    float kk[8] = {k0.x,k0.y,k0.z,k0.w,k1.x,k1.y,k1.z,k1.w};
    float s=0.f;
    #pragma unroll
    for (int j=0;j<4;j++){
        float2 f = __bfloat1622float2(*reinterpret_cast<bf162*>(&a[j]));
        s += f.x*kk[2*j] + f.y*kk[2*j+1];
    }
    #pragma unroll
    for (int o=16;o>0;o>>=1) s += __shfl_xor_sync(0xffffffffu, s, o);
    if (lane==0) D[row]=s;
}

// ---------------- launch ---------------------------------------------------
extern "C" void kernel_launch(void* const* d_in, const int* in_sizes, int n_in,
                              void* d_out, int out_size)
{
    const float* x     = (const float*)d_in[0];
    const float* qw    = (const float*)d_in[1];
    const float* qb    = (const float*)d_in[2];
    const float* kw    = (const float*)d_in[3];
    const float* kb    = (const float*)d_in[4];
    const float* vw    = (const float*)d_in[5];
    const float* vb    = (const float*)d_in[6];
    const float* pw    = (const float*)d_in[7];
    const float* pb    = (const float*)d_in[8];
    const float* gamma = (const float*)d_in[9];
    const float* beta  = (const float*)d_in[10];
    const float* w     = (const float*)d_in[11];
    float* out = (float*)d_out;

    bf16 *xhl,*qbf,*kbf,*ybf,*vtb,*qpb,*kpb,*kptb,*kptvb;
    bf16 *qwb,*kwb,*pwb,*wb,*vwh,*vwlh;
    float *v,*t1,*xdq,*xdk,*D,*ks,*kptvp;
    cudaGetSymbolAddress((void**)&xhl,  g_xhl);
    cudaGetSymbolAddress((void**)&qbf,  g_qb);
    cudaGetSymbolAddress((void**)&kbf,  g_kb);
    cudaGetSymbolAddress((void**)&ybf,  g_yb);
    cudaGetSymbolAddress((void**)&vtb,  g_vtb);
    cudaGetSymbolAddress((void**)&qpb,  g_qpb);
    cudaGetSymbolAddress((void**)&kpb,  g_kpb);
    cudaGetSymbolAddress((void**)&kptb, g_kptb);
    cudaGetSymbolAddress((void**)&kptvb,g_kptvb);
    cudaGetSymbolAddress((void**)&qwb,  g_qwb);
    cudaGetSymbolAddress((void**)&kwb,  g_kwb);
    cudaGetSymbolAddress((void**)&pwb,  g_pwb);
    cudaGetSymbolAddress((void**)&wb,   g_wb);
    cudaGetSymbolAddress((void**)&vwh,  g_vwh);
    cudaGetSymbolAddress((void**)&vwlh, g_vwlh);
    cudaGetSymbolAddress((void**)&v,    g_v);
    cudaGetSymbolAddress((void**)&t1,   g_t1);
    cudaGetSymbolAddress((void**)&xdq,  g_xdq);
    cudaGetSymbolAddress((void**)&xdk,  g_xdk);
    cudaGetSymbolAddress((void**)&D,    g_D);
    cudaGetSymbolAddress((void**)&ks,   g_ks);
    cudaGetSymbolAddress((void**)&kptvp,g_kptvp);

    cudaFuncSetAttribute(gemm_bf<0>, cudaFuncAttributeMaxDynamicSharedMemorySize, SMEM_B);
    cudaFuncSetAttribute(gemm_bf<1>, cudaFuncAttributeMaxDynamicSharedMemorySize, SMEM_B);
    cudaFuncSetAttribute(gemm_bf<2>, cudaFuncAttributeMaxDynamicSharedMemorySize, SMEM_B);
    cudaFuncSetAttribute(gemm_bf<3>, cudaFuncAttributeMaxDynamicSharedMemorySize, SMEM_B);
    cudaFuncSetAttribute(gemm_bf<4>, cudaFuncAttributeMaxDynamicSharedMemorySize, SMEM_B);

    dim3 blk(256);
    dim3 gblk(128);

    // 1) weight conversions (single launch)
    {
        int total = 3*EE*EE + MF*EE + EE*EE;
        conv_all<<<(total+255)/256,blk>>>(qw, kw, pw, w, vw,
                                          qwb, kwb, pwb, wb, vwh, vwlh);
    }

    // 2) LayerNorm -> xhl (interleaved hi/lo, row stride 1024)
    ln_kernel<<<NR,128>>>(x, gamma, beta, xhl);

    // 3) q/k projections (bf16 out)
    dim3 gqkv(NR/128, EE/128, 1);
    gemm_bf<0><<<gqkv,gblk,SMEM_B>>>(xhl, qwb, qbf, EE, 2*EE, EE, EE, qb, nullptr, nullptr, nullptr, 0,0,0,0,1);
    gemm_bf<0><<<gqkv,gblk,SMEM_B>>>(xhl, kwb, kbf, EE, 2*EE, EE, EE, kb, nullptr, nullptr, nullptr, 0,0,0,0,1);

    // 4) v: t1 = xnh@vwl + xnl@vwh (one K=1024 GEMM); v = xnh@vwh + vb + t1
    gemm_bf<4><<<gqkv,gblk,SMEM_B>>>(xhl, vwlh, t1, 2*EE, 2*EE, 2*EE, EE, nullptr, nullptr, nullptr, nullptr, 0,0,0,0,1);
    gemm_bf<3><<<gqkv,gblk,SMEM_B>>>(xhl, vwh,  v,  EE,   2*EE, EE,   EE, vb, nullptr, nullptr, t1, 0,0,0,0,1);

    // 5) row half-norms from bf16 q,k
    xd_kernel<<<NR/8,256>>>(qbf, kbf, xdq, xdk);

    // 6) features (exp epilogue, bf16 out)
    dim3 gqp(NR/128, MF/128, 1);
    gemm_bf<1><<<gqp,gblk,SMEM_B>>>(qbf, wb, qpb, EE, EE, EE, MF, nullptr, xdq, nullptr, nullptr, 0,0,0,0,1);
    gemm_bf<1><<<gqp,gblk,SMEM_B>>>(kbf, wb, kpb, EE, EE, EE, MF, nullptr, xdk, nullptr, nullptr, 0,0,0,0,1);

    // 7) ksum[b,m]
    ksum_kernel<<<dim3(BB, MF/64),blk>>>(kpb, ks);

    // 8) transposes: vtb[b][E][S] (f32->bf16), kptb[b][M][S] (bf16->bf16)
    transpose_t<float,bf16><<<dim3(EE/32, SS/32, BB),blk>>>(v,   vtb,  SS, EE);
    transpose_t<bf16,bf16> <<<dim3(MF/32, SS/32, BB),blk>>>(kpb, kptb, SS, MF);

    // 9) kptv split-K partials (f32), reduce -> bf16
    gemm_bf<4><<<dim3(EE/128, MF/128, BB*SPLITK),gblk,SMEM_B>>>(
        vtb, kptb, kptvp, SS/SPLITK, SS, SS, MF, nullptr, nullptr, nullptr, nullptr,
        (size_t)EE*SS, (size_t)MF*SS, (size_t)EE*MF, 0, SPLITK);
    reduce_kptv<<<dim3((EE*MF)/256, BB),blk>>>(kptvp, kptvb);

    // 10) D[r]
    d_kernel<<<NR/8,256>>>(qpb, ks, D);

    // 11) y[b,s,e] = (qp @ kptv^T)/(D+eps), bf16 out
    gemm_bf<2><<<dim3(SS/128, EE/128, BB),gblk,SMEM_B>>>(
        qpb, kptvb, ybf, MF, MF, MF, EE, nullptr, nullptr, D, nullptr,
        (size_t)SS*MF, (size_t)EE*MF, (size_t)SS*EE, SS, 1);

    // 12) out = v + y @ pw^T + pb   (f32 out)
    gemm_bf<3><<<gqkv,gblk,SMEM_B>>>(ybf, pwb, out, EE, EE, EE, EE, pb, nullptr, nullptr, v, 0,0,0,0,1);
}

// round 10
// speedup vs baseline: 1.7490x; 1.6133x over previous
#include <cuda_runtime.h>
#include <cuda_bf16.h>
#include <math.h>
#include <stdint.h>

#define BB 8
#define SS 4096
#define NR (BB*SS)      // 32768 rows
#define EE 512
#define MF 256
#define SPLITK 8
#define NSTAGE 3
#define KCB 64                      // k elements (bf16) per chunk = 128B rows
#define STG_B 32768                 // bytes per stage: A 16KB + B 16KB
#define SMEM_B (NSTAGE*STG_B)       // 96KB

typedef __nv_bfloat16 bf16;
typedef __nv_bfloat162 bf162;

// ---------------- scratch (device globals; no allocation allowed) ----------
__device__ bf16  g_xhl [(size_t)NR*2*EE];  // [row][0:512]=hi, [512:1024]=lo
__device__ bf16  g_qb  [(size_t)NR*EE];
__device__ bf16  g_kb  [(size_t)NR*EE];
__device__ bf16  g_yb  [(size_t)NR*EE];
__device__ bf16  g_vtb [(size_t)NR*EE];    // [b][E][S]
__device__ bf16  g_qpb [(size_t)NR*MF];
__device__ bf16  g_kpb [(size_t)NR*MF];
__device__ bf16  g_kptb[(size_t)NR*MF];    // [b][M][S]
__device__ float g_v   [(size_t)NR*EE];
__device__ float g_t1  [(size_t)NR*EE];
__device__ float g_xdq[NR];
__device__ float g_xdk[NR];
__device__ float g_D  [NR];
__device__ float g_ks [BB*MF];
__device__ float g_kptvp[(size_t)SPLITK*BB*EE*MF];
__device__ bf16  g_kptvb[(size_t)BB*EE*MF];
__device__ bf16  g_qwb[EE*EE];
__device__ bf16  g_kwb[EE*EE];
__device__ bf16  g_pwb[EE*EE];
__device__ bf16  g_wb [MF*EE];
__device__ bf16  g_vwh[EE*EE];
__device__ bf16  g_vwlh[EE*2*EE];          // [col][0:512]=vwl, [512:1024]=vwh

// =================== portable tensor-core helpers (sm_80+) =================
__device__ __forceinline__ void ldsm4(uint32_t* r, uint32_t addr){
    asm volatile("ldmatrix.sync.aligned.m8n8.x4.shared.b16 {%0,%1,%2,%3}, [%4];"
        : "=r"(r[0]), "=r"(r[1]), "=r"(r[2]), "=r"(r[3]) : "r"(addr));
}
__device__ __forceinline__ void mma16(float* d, const uint32_t* a, const uint32_t* b){
    asm volatile("mma.sync.aligned.m16n8k16.row.col.f32.bf16.bf16.f32 "
        "{%0,%1,%2,%3}, {%4,%5,%6,%7}, {%8,%9}, {%0,%1,%2,%3};"
        : "+f"(d[0]), "+f"(d[1]), "+f"(d[2]), "+f"(d[3])
        : "r"(a[0]), "r"(a[1]), "r"(a[2]), "r"(a[3]), "r"(b[0]), "r"(b[1]));
}
__device__ __forceinline__ void cpa16(uint32_t dst, const void* src){
    asm volatile("cp.async.cg.shared.global [%0], [%1], 16;"
                 :: "r"(dst), "l"(src) : "memory");
}
#define CP_COMMIT() asm volatile("cp.async.commit_group;" ::: "memory")
#define CP_WAIT1()  asm volatile("cp.async.wait_group 1;" ::: "memory")

// =================== bf16 mma.sync GEMM, tile 128x128, 4 warps =============
// C[r,c] = sum_k A[r,k]*W[c,k], bf16 K-major (row strides lda/ldw elements).
// 4 warps as 2m x 2n, warp tile 64x64, K chunks of 64, fp32 accum. 2 CTA/SM.
// Fill is instruction-level coalesced: each cp.async instruction's 32 lanes
// cover 4 full consecutive 128B lines (4 L1 wavefronts, not 32).
// MODE 0: +bias[c]            -> bf16 out   (q/k proj)
// MODE 1: expf(acc-xd[r])/16  -> bf16 out   (features)
// MODE 2: acc/(Dv[z,r]+eps)   -> bf16 out   (y)
// MODE 3: +bias[c]+addsrc     -> f32 out    (v main, final)
// MODE 4: plain               -> f32 out    (kptv partials / t1; split-K ok)
template<int MODE>
__global__ __launch_bounds__(128, 2) void gemm_bf(
    const bf16* __restrict__ A, const bf16* __restrict__ W, void* __restrict__ Cv,
    int K, int lda, int ldw, int ncols,
    const float* __restrict__ bias, const float* __restrict__ xd,
    const float* __restrict__ Dv, const float* __restrict__ addsrc,
    size_t aB, size_t wB, size_t cB, int dB, int splitk)
{
    extern __shared__ char smc[];
    const uint32_t sb = (uint32_t)__cvta_generic_to_shared(smc);
    const int tid = threadIdx.x, lane = tid & 31, wid = tid >> 5;
    const int z = blockIdx.z;
    const bf16* Ab = A;
    const bf16* Wb = W;
    size_t cOff;
    if (MODE == 4 && splitk > 1) {
        int b = z / splitk, sk = z - b*splitk;
        Ab += b*aB + (size_t)sk*K;
        Wb += b*wB + (size_t)sk*K;
        cOff = (size_t)z*cB;
    } else {
        Ab += (size_t)z*aB; Wb += (size_t)z*wB; cOff = (size_t)z*cB;
    }
    const int rowBase = blockIdx.x*128, colBase = blockIdx.y*128;

    // coalesced fill mapping: octet o = tid>>3 handles rows {o, o+16, ..., o+112},
    // lane-in-octet c = tid&7 handles 16B chunk c of each row.
    const int r0 = tid >> 3, cch = tid & 7;
    const bf16* gA = Ab + (size_t)(rowBase + r0)*lda + cch*8;
    const bf16* gB = Wb + (size_t)(colBase + r0)*ldw + cch*8;
    const size_t stepA = (size_t)16*lda;   // 16 rows per j-iteration
    const size_t stepB = (size_t)16*ldw;
    const uint32_t sAd = sb + (uint32_t)r0*128u + (uint32_t)((cch ^ (r0 & 7)) << 4);
    const uint32_t sBd = sAd + 16384u;
    const int nCh = K / KCB;

    #define LOAD_STAGE(i) do {                                            \
        if ((i) < nCh) {                                                  \
            const uint32_t stg = ((i) % NSTAGE)*STG_B;                    \
            const bf16* pA = gA + (size_t)(i)*KCB;                        \
            const bf16* pB = gB + (size_t)(i)*KCB;                        \
            _Pragma("unroll")                                             \
            for (int j = 0; j < 8; j++) {                                 \
                cpa16(sAd + stg + (uint32_t)(j*2048), pA + (size_t)j*stepA); \
                cpa16(sBd + stg + (uint32_t)(j*2048), pB + (size_t)j*stepB); \
            }                                                             \
        }                                                                 \
        CP_COMMIT();                                                      \
    } while (0)

    LOAD_STAGE(0);
    LOAD_STAGE(1);

    const int wm = wid & 1, wn = wid >> 1;
    const int rq = lane >> 2;
    const int sw = lane & 7;
    const int lrow8 = (lane & 7) + ((lane >> 3) & 1) * 8;
    const int khalf = lane >> 4;
    uint32_t aOff[4], bOff[4];
    #pragma unroll
    for (int mi = 0; mi < 4; mi++)
        aOff[mi] = (uint32_t)(wm*64 + mi*16 + lrow8) * 128u;
    #pragma unroll
    for (int nb = 0; nb < 4; nb++)
        bOff[nb] = 16384u + (uint32_t)(wn*64 + nb*16 + lrow8) * 128u;

    float acc[4][8][4];
    #pragma unroll
    for (int mi = 0; mi < 4; mi++)
        #pragma unroll
        for (int ni = 0; ni < 8; ni++)
            #pragma unroll
            for (int t = 0; t < 4; t++) acc[mi][ni][t] = 0.f;

    for (int i = 0; i < nCh; i++) {
        CP_WAIT1();
        __syncthreads();
        const uint32_t sA = sb + (i % NSTAGE)*STG_B;
        #pragma unroll
        for (int ks = 0; ks < 4; ks++) {
            const uint32_t kq = (uint32_t)(((ks*2 + khalf) ^ sw) << 4);
            uint32_t af[4][4], bfr[8][2];
            #pragma unroll
            for (int mi = 0; mi < 4; mi++)
                ldsm4(af[mi], sA + aOff[mi] + kq);
            #pragma unroll
            for (int nb = 0; nb < 4; nb++) {
                uint32_t m[4];
                ldsm4(m, sA + bOff[nb] + kq);
                bfr[2*nb  ][0] = m[0]; bfr[2*nb+1][0] = m[1];
                bfr[2*nb  ][1] = m[2]; bfr[2*nb+1][1] = m[3];
            }
            #pragma unroll
            for (int mi = 0; mi < 4; mi++)
                #pragma unroll
                for (int ni = 0; ni < 8; ni++)
                    mma16(acc[mi][ni], af[mi], bfr[ni]);
        }
        LOAD_STAGE(i + NSTAGE - 1);
    }

    // ---------------- epilogue ---------------------------------------------
    bf16*  Cb = (bf16*)Cv + cOff;
    float* Cf = (float*)Cv + cOff;
    const int c2 = (lane & 3)*2;
    #pragma unroll
    for (int mi = 0; mi < 4; mi++) {
        const int r0e = rowBase + wm*64 + mi*16 + rq;
        const int r1e = r0e + 8;
        float e0 = 0.f, e1 = 0.f, d0 = 1.f, d1 = 1.f;
        if (MODE == 1) { e0 = xd[r0e]; e1 = xd[r1e]; }
        if (MODE == 2) {
            d0 = 1.f/(Dv[(size_t)z*dB + r0e] + 1e-8f);
            d1 = 1.f/(Dv[(size_t)z*dB + r1e] + 1e-8f);
        }
        #pragma unroll
        for (int ni = 0; ni < 8; ni++) {
            const int cc = colBase + wn*64 + ni*8 + c2;
            float t0 = acc[mi][ni][0], t1v = acc[mi][ni][1];
            float t2 = acc[mi][ni][2], t3  = acc[mi][ni][3];
            if (MODE == 0) {
                float2 bv = *reinterpret_cast<const float2*>(bias + cc);
                t0 += bv.x; t1v += bv.y; t2 += bv.x; t3 += bv.y;
            } else if (MODE == 1) {
                t0 = expf(t0 - e0)*0.0625f; t1v = expf(t1v - e0)*0.0625f;
                t2 = expf(t2 - e1)*0.0625f; t3  = expf(t3  - e1)*0.0625f;
            } else if (MODE == 2) {
                t0 *= d0; t1v *= d0; t2 *= d1; t3 *= d1;
            } else if (MODE == 3) {
                float2 bv = *reinterpret_cast<const float2*>(bias + cc);
                float2 s0 = *reinterpret_cast<const float2*>(addsrc + (size_t)r0e*ncols + cc);
                float2 s1 = *reinterpret_cast<const float2*>(addsrc + (size_t)r1e*ncols + cc);
                t0 += bv.x + s0.x; t1v += bv.y + s0.y;
                t2 += bv.x + s1.x; t3  += bv.y + s1.y;
            }
            if (MODE <= 2) {
                *reinterpret_cast<bf162*>(Cb + (size_t)r0e*ncols + cc) = __floats2bfloat162_rn(t0, t1v);
                *reinterpret_cast<bf162*>(Cb + (size_t)r1e*ncols + cc) = __floats2bfloat162_rn(t2, t3);
            } else {
                *reinterpret_cast<float2*>(Cf + (size_t)r0e*ncols + cc) = make_float2(t0, t1v);
                *reinterpret_cast<float2*>(Cf + (size_t)r1e*ncols + cc) = make_float2(t2, t3);
            }
        }
    }
    #undef LOAD_STAGE
}

// ---------------- one fused weight-conversion kernel -----------------------
__global__ __launch_bounds__(256) void conv_all(
    const float* __restrict__ qw, const float* __restrict__ kw,
    const float* __restrict__ pw, const float* __restrict__ w,
    const float* __restrict__ vw,
    bf16* __restrict__ qwb, bf16* __restrict__ kwb, bf16* __restrict__ pwb,
    bf16* __restrict__ wb, bf16* __restrict__ vwh, bf16* __restrict__ vwlh)
{
    int i = blockIdx.x*256 + threadIdx.x;
    const int N1 = EE*EE;           // 262144
    if (i < N1) {
        qwb[i] = __float2bfloat16_rn(qw[i]);
    } else if (i < 2*N1) {
        int j = i - N1; kwb[j] = __float2bfloat16_rn(kw[j]);
    } else if (i < 3*N1) {
        int j = i - 2*N1; pwb[j] = __float2bfloat16_rn(pw[j]);
    } else if (i < 3*N1 + MF*EE) {
        int j = i - 3*N1; wb[j] = __float2bfloat16_rn(w[j]);
    } else {
        int j = i - 3*N1 - MF*EE;
        int row = j >> 9, col = j & 511;
        float v = vw[j];
        bf16 hv = __float2bfloat16_rn(v);
        bf16 lv = __float2bfloat16_rn(v - __bfloat162float(hv));
        vwh[j] = hv;
        vwlh[(size_t)row*1024 + col]       = lv;   // pairs with xnh
        vwlh[(size_t)row*1024 + 512 + col] = hv;   // pairs with xnl
    }
}

// ---------------- LayerNorm -> interleaved (hi, lo) bf16 -------------------
__global__ __launch_bounds__(128) void ln_kernel(
    const float* __restrict__ x, const float* __restrict__ gamma,
    const float* __restrict__ beta, bf16* __restrict__ xhl)
{
    int row = blockIdx.x;
    const float4* xr = reinterpret_cast<const float4*>(x + (size_t)row*EE);
    int t = threadIdx.x;
    float4 v = xr[t];
    float s  = v.x+v.y+v.z+v.w;
    float s2 = v.x*v.x+v.y*v.y+v.z*v.z+v.w*v.w;
    #pragma unroll
    for (int o=16;o>0;o>>=1){
        s  += __shfl_xor_sync(0xffffffffu, s,  o);
        s2 += __shfl_xor_sync(0xffffffffu, s2, o);
    }
    __shared__ float rs[4], rs2[4];
    int wid = t>>5, lane = t&31;
    if (lane==0){ rs[wid]=s; rs2[wid]=s2; }
    __syncthreads();
    s  = rs[0]+rs[1]+rs[2]+rs[3];
    s2 = rs2[0]+rs2[1]+rs2[2]+rs2[3];
    float mu  = s * (1.f/EE);
    float var = s2*(1.f/EE) - mu*mu;
    float inv = rsqrtf(var + 1e-5f);
    float4 g  = reinterpret_cast<const float4*>(gamma)[t];
    float4 bt = reinterpret_cast<const float4*>(beta)[t];
    float o[4];
    o[0] = (v.x-mu)*inv*g.x + bt.x;
    o[1] = (v.y-mu)*inv*g.y + bt.y;
    o[2] = (v.z-mu)*inv*g.z + bt.z;
    o[3] = (v.w-mu)*inv*g.w + bt.w;
    bf16 h[4]; float l[4];
    #pragma unroll
    for (int j=0;j<4;j++){ h[j]=__float2bfloat16_rn(o[j]); l[j]=o[j]-__bfloat162float(h[j]); }
    bf162* ph = reinterpret_cast<bf162*>(xhl + (size_t)row*1024 + t*4);
    bf162* pl = reinterpret_cast<bf162*>(xhl + (size_t)row*1024 + 512 + t*4);
    ph[0] = bf162(h[0], h[1]);  ph[1] = bf162(h[2], h[3]);
    pl[0] = __floats2bfloat162_rn(l[0], l[1]);
    pl[1] = __floats2bfloat162_rn(l[2], l[3]);
}

// ---------------- 0.5*||row||^2 of bf16 q,k --------------------------------
__device__ __forceinline__ float sumsq8(uint4 u){
    float s = 0.f;
    uint32_t a[4] = {u.x, u.y, u.z, u.w};
    #pragma unroll
    for (int j=0;j<4;j++){
        float2 f = __bfloat1622float2(*reinterpret_cast<bf162*>(&a[j]));
        s += f.x*f.x + f.y*f.y;
    }
    return s;
}
__global__ __launch_bounds__(256) void xd_kernel(
    const bf16* __restrict__ q, const bf16* __restrict__ k,
    float* __restrict__ xdq, float* __restrict__ xdk)
{
    int row  = blockIdx.x*8 + (threadIdx.x>>5);
    int lane = threadIdx.x&31;
    const uint4* qr = reinterpret_cast<const uint4*>(q + (size_t)row*EE);
    const uint4* kr = reinterpret_cast<const uint4*>(k + (size_t)row*EE);
    float sq=0.f, sk=0.f;
    #pragma unroll
    for (int j=0;j<2;j++){
        sq += sumsq8(qr[lane + j*32]);
        sk += sumsq8(kr[lane + j*32]);
    }
    #pragma unroll
    for (int o=16;o>0;o>>=1){
        sq += __shfl_xor_sync(0xffffffffu, sq, o);
        sk += __shfl_xor_sync(0xffffffffu, sk, o);
    }
    if (lane==0){ xdq[row]=0.5f*sq; xdk[row]=0.5f*sk; }
}

// ---------------- column sums of kp (bf16) per batch -----------------------
__global__ __launch_bounds__(256) void ksum_kernel(
    const bf16* __restrict__ kp, float* __restrict__ out)
{
    int b = blockIdx.x, m0 = blockIdx.y*64;
    int tx = threadIdx.x & 63, ty = threadIdx.x >> 6;
    const bf16* base = kp + (size_t)b*SS*MF + m0 + tx;
    float s=0.f;
    for (int srow=ty; srow<SS; srow+=4) s += __bfloat162float(base[(size_t)srow*MF]);
    __shared__ float red[4][64];
    red[ty][tx]=s;
    __syncthreads();
    if (ty==0) out[b*MF+m0+tx] = red[0][tx]+red[1][tx]+red[2][tx]+red[3][tx];
}

// ---------------- batched 2D transpose with dtype convert ------------------
__device__ __forceinline__ float ldf(const float* p){ return *p; }
__device__ __forceinline__ float ldf(const bf16* p){ return __bfloat162float(*p); }
__device__ __forceinline__ void stf(float* p, float v){ *p = v; }
__device__ __forceinline__ void stf(bf16* p, float v){ *p = __float2bfloat16_rn(v); }

template<typename TI, typename TO>
__global__ __launch_bounds__(256) void transpose_t(
    const TI* __restrict__ in, TO* __restrict__ out, int R, int Cc)
{
    __shared__ float t[32][33];
    int z = blockIdx.z;
    in  += (size_t)z*R*Cc;
    out += (size_t)z*R*Cc;
    int tx = threadIdx.x & 31, ty = threadIdx.x >> 5;
    int x  = blockIdx.x*32 + tx;
    int y0 = blockIdx.y*32;
    #pragma unroll
    for (int j=0;j<4;j++)
        t[ty + j*8][tx] = ldf(in + (size_t)(y0 + ty + j*8)*Cc + x);
    __syncthreads();
    int xo = y0 + tx;
    int c0 = blockIdx.x*32;
    #pragma unroll
    for (int j=0;j<4;j++)
        stf(out + (size_t)(c0 + ty + j*8)*R + xo, t[tx][ty + j*8]);
}

// ---------------- reduce split-K partials -> bf16 --------------------------
__global__ __launch_bounds__(256) void reduce_kptv(
    const float* __restrict__ p, bf16* __restrict__ o)
{
    const size_t EM = (size_t)EE*MF;
    size_t i = (size_t)blockIdx.x*256 + threadIdx.x;
    int b = blockIdx.y;
    const float* pb = p + (size_t)b*SPLITK*EM + i;
    float s = 0.f;
    #pragma unroll
    for (int sk=0; sk<SPLITK; sk++) s += pb[(size_t)sk*EM];
    o[(size_t)b*EM + i] = __float2bfloat16_rn(s);
}

// ---------------- D[r] = qp[r,:] . ksum[b,:] -------------------------------
__global__ __launch_bounds__(256) void d_kernel(
    const bf16* __restrict__ qp, const float* __restrict__ ks,
    float* __restrict__ D)
{
    int row  = blockIdx.x*8 + (threadIdx.x>>5);
    int lane = threadIdx.x&31;
    int b = row >> 12;
    uint4 u = *reinterpret_cast<const uint4*>(qp + (size_t)row*MF + lane*8);
    float4 k0 = *reinterpret_cast<const float4*>(ks + b*MF + lane*8);
    float4 k1 = *reinterpret_cast<const float4*>(ks + b*MF + lane*8 + 4);
    uint32_t a[4] = {u.x, u.y, u.z, u.w};
    float kk[8] = {k0.x,k0.y,k0.z,k0.w,k1.x,k1.y,k1.z,k1.w};
    float s=0.f;
    #pragma unroll
    for (int j=0;j<4;j++){
        float2 f = __bfloat1622float2(*reinterpret_cast<bf162*>(&a[j]));
        s += f.x*kk[2*j] + f.y*kk[2*j+1];
    }
    #pragma unroll
    for (int o=16;o>0;o>>=1) s += __shfl_xor_sync(0xffffffffu, s, o);
    if (lane==0) D[row]=s;
}

// ---------------- launch ---------------------------------------------------
extern "C" void kernel_launch(void* const* d_in, const int* in_sizes, int n_in,
                              void* d_out, int out_size)
{
    const float* x     = (const float*)d_in[0];
    const float* qw    = (const float*)d_in[1];
    const float* qb    = (const float*)d_in[2];
    const float* kw    = (const float*)d_in[3];
    const float* kb    = (const float*)d_in[4];
    const float* vw    = (const float*)d_in[5];
    const float* vb    = (const float*)d_in[6];
    const float* pw    = (const float*)d_in[7];
    const float* pb    = (const float*)d_in[8];
    const float* gamma = (const float*)d_in[9];
    const float* beta  = (const float*)d_in[10];
    const float* w     = (const float*)d_in[11];
    float* out = (float*)d_out;

    bf16 *xhl,*qbf,*kbf,*ybf,*vtb,*qpb,*kpb,*kptb,*kptvb;
    bf16 *qwb,*kwb,*pwb,*wb,*vwh,*vwlh;
    float *v,*t1,*xdq,*xdk,*D,*ks,*kptvp;
    cudaGetSymbolAddress((void**)&xhl,  g_xhl);
    cudaGetSymbolAddress((void**)&qbf,  g_qb);
    cudaGetSymbolAddress((void**)&kbf,  g_kb);
    cudaGetSymbolAddress((void**)&ybf,  g_yb);
    cudaGetSymbolAddress((void**)&vtb,  g_vtb);
    cudaGetSymbolAddress((void**)&qpb,  g_qpb);
    cudaGetSymbolAddress((void**)&kpb,  g_kpb);
    cudaGetSymbolAddress((void**)&kptb, g_kptb);
    cudaGetSymbolAddress((void**)&kptvb,g_kptvb);
    cudaGetSymbolAddress((void**)&qwb,  g_qwb);
    cudaGetSymbolAddress((void**)&kwb,  g_kwb);
    cudaGetSymbolAddress((void**)&pwb,  g_pwb);
    cudaGetSymbolAddress((void**)&wb,   g_wb);
    cudaGetSymbolAddress((void**)&vwh,  g_vwh);
    cudaGetSymbolAddress((void**)&vwlh, g_vwlh);
    cudaGetSymbolAddress((void**)&v,    g_v);
    cudaGetSymbolAddress((void**)&t1,   g_t1);
    cudaGetSymbolAddress((void**)&xdq,  g_xdq);
    cudaGetSymbolAddress((void**)&xdk,  g_xdk);
    cudaGetSymbolAddress((void**)&D,    g_D);
    cudaGetSymbolAddress((void**)&ks,   g_ks);
    cudaGetSymbolAddress((void**)&kptvp,g_kptvp);

    cudaFuncSetAttribute(gemm_bf<0>, cudaFuncAttributeMaxDynamicSharedMemorySize, SMEM_B);
    cudaFuncSetAttribute(gemm_bf<1>, cudaFuncAttributeMaxDynamicSharedMemorySize, SMEM_B);
    cudaFuncSetAttribute(gemm_bf<2>, cudaFuncAttributeMaxDynamicSharedMemorySize, SMEM_B);
    cudaFuncSetAttribute(gemm_bf<3>, cudaFuncAttributeMaxDynamicSharedMemorySize, SMEM_B);
    cudaFuncSetAttribute(gemm_bf<4>, cudaFuncAttributeMaxDynamicSharedMemorySize, SMEM_B);

    dim3 blk(256);
    dim3 gblk(128);

    // 1) weight conversions (single launch)
    {
        int total = 3*EE*EE + MF*EE + EE*EE;
        conv_all<<<(total+255)/256,blk>>>(qw, kw, pw, w, vw,
                                          qwb, kwb, pwb, wb, vwh, vwlh);
    }

    // 2) LayerNorm -> xhl (interleaved hi/lo, row stride 1024)
    ln_kernel<<<NR,128>>>(x, gamma, beta, xhl);

    // 3) q/k projections (bf16 out)
    dim3 gqkv(NR/128, EE/128, 1);
    gemm_bf<0><<<gqkv,gblk,SMEM_B>>>(xhl, qwb, qbf, EE, 2*EE, EE, EE, qb, nullptr, nullptr, nullptr, 0,0,0,0,1);
    gemm_bf<0><<<gqkv,gblk,SMEM_B>>>(xhl, kwb, kbf, EE, 2*EE, EE, EE, kb, nullptr, nullptr, nullptr, 0,0,0,0,1);

    // 4) v: t1 = xnh@vwl + xnl@vwh (one K=1024 GEMM); v = xnh@vwh + vb + t1
    gemm_bf<4><<<gqkv,gblk,SMEM_B>>>(xhl, vwlh, t1, 2*EE, 2*EE, 2*EE, EE, nullptr, nullptr, nullptr, nullptr, 0,0,0,0,1);
    gemm_bf<3><<<gqkv,gblk,SMEM_B>>>(xhl, vwh,  v,  EE,   2*EE, EE,   EE, vb, nullptr, nullptr, t1, 0,0,0,0,1);

    // 5) row half-norms from bf16 q,k
    xd_kernel<<<NR/8,256>>>(qbf, kbf, xdq, xdk);

    // 6) features (exp epilogue, bf16 out)
    dim3 gqp(NR/128, MF/128, 1);
    gemm_bf<1><<<gqp,gblk,SMEM_B>>>(qbf, wb, qpb, EE, EE, EE, MF, nullptr, xdq, nullptr, nullptr, 0,0,0,0,1);
    gemm_bf<1><<<gqp,gblk,SMEM_B>>>(kbf, wb, kpb, EE, EE, EE, MF, nullptr, xdk, nullptr, nullptr, 0,0,0,0,1);

    // 7) ksum[b,m]
    ksum_kernel<<<dim3(BB, MF/64),blk>>>(kpb, ks);

    // 8) transposes: vtb[b][E][S] (f32->bf16), kptb[b][M][S] (bf16->bf16)
    transpose_t<float,bf16><<<dim3(EE/32, SS/32, BB),blk>>>(v,   vtb,  SS, EE);
    transpose_t<bf16,bf16> <<<dim3(MF/32, SS/32, BB),blk>>>(kpb, kptb, SS, MF);

    // 9) kptv split-K partials (f32), reduce -> bf16
    gemm_bf<4><<<dim3(EE/128, MF/128, BB*SPLITK),gblk,SMEM_B>>>(
        vtb, kptb, kptvp, SS/SPLITK, SS, SS, MF, nullptr, nullptr, nullptr, nullptr,
        (size_t)EE*SS, (size_t)MF*SS, (size_t)EE*MF, 0, SPLITK);
    reduce_kptv<<<dim3((EE*MF)/256, BB),blk>>>(kptvp, kptvb);

    // 10) D[r]
    d_kernel<<<NR/8,256>>>(qpb, ks, D);

    // 11) y[b,s,e] = (qp @ kptv^T)/(D+eps), bf16 out
    gemm_bf<2><<<dim3(SS/128, EE/128, BB),gblk,SMEM_B>>>(
        qpb, kptvb, ybf, MF, MF, MF, EE, nullptr, nullptr, D, nullptr,
        (size_t)SS*MF, (size_t)EE*MF, (size_t)SS*EE, SS, 1);

    // 12) out = v + y @ pw^T + pb   (f32 out)
    gemm_bf<3><<<gqkv,gblk,SMEM_B>>>(ybf, pwb, out, EE, EE, EE, EE, pb, nullptr, nullptr, v, 0,0,0,0,1);
}

// round 11
// speedup vs baseline: 1.8083x; 1.0339x over previous
#include <cuda_runtime.h>
#include <cuda_bf16.h>
#include <math.h>
#include <stdint.h>

#define BB 8
#define SS 4096
#define NR (BB*SS)      // 32768 rows
#define EE 512
#define MF 256
#define SPLITK 8
#define NSTAGE 3
#define KCB 64                      // k elements (bf16) per chunk = 128B rows
#define STG_B 32768                 // bytes per stage: A 16KB + B 16KB
#define SMEM_B (NSTAGE*STG_B)       // 96KB
#define N1 (EE*EE)

typedef __nv_bfloat16 bf16;
typedef __nv_bfloat162 bf162;

// ---------------- scratch (device globals; no allocation allowed) ----------
__device__ bf16  g_xhl [(size_t)NR*3*EE];  // [row][0:512]=hi, [512:1024]=lo, [1024:1536]=hi
__device__ bf16  g_qk  [(size_t)2*NR*EE];  // stacked q, k (bf16)
__device__ bf16  g_qkp [(size_t)2*NR*MF];  // stacked qp, kp (bf16)
__device__ bf16  g_yb  [(size_t)NR*EE];
__device__ bf16  g_vtb [(size_t)NR*EE];    // [b][E][S]
__device__ bf16  g_kptb[(size_t)NR*MF];    // [b][M][S]
__device__ float g_v   [(size_t)NR*EE];
__device__ float g_xd2 [2*NR];             // stacked xdq, xdk
__device__ float g_D  [NR];
__device__ float g_ks [BB*MF];
__device__ float g_kptvp[(size_t)SPLITK*BB*EE*MF];
__device__ bf16  g_kptvb[(size_t)BB*EE*MF];
__device__ bf16  g_qkw[2*N1];              // stacked qw, kw (bf16)
__device__ bf16  g_pwb[N1];
__device__ bf16  g_wb [MF*EE];
__device__ bf16  g_vw1536[EE*3*EE];        // [c][0:512]=vwh, [512:1024]=vwh, [1024:1536]=vwl
__device__ float g_qkb[2*EE];              // stacked qb, kb

// =================== portable tensor-core helpers (sm_80+) =================
__device__ __forceinline__ void ldsm4(uint32_t* r, uint32_t addr){
    asm volatile("ldmatrix.sync.aligned.m8n8.x4.shared.b16 {%0,%1,%2,%3}, [%4];"
        : "=r"(r[0]), "=r"(r[1]), "=r"(r[2]), "=r"(r[3]) : "r"(addr));
}
__device__ __forceinline__ void mma16(float* d, const uint32_t* a, const uint32_t* b){
    asm volatile("mma.sync.aligned.m16n8k16.row.col.f32.bf16.bf16.f32 "
        "{%0,%1,%2,%3}, {%4,%5,%6,%7}, {%8,%9}, {%0,%1,%2,%3};"
        : "+f"(d[0]), "+f"(d[1]), "+f"(d[2]), "+f"(d[3])
        : "r"(a[0]), "r"(a[1]), "r"(a[2]), "r"(a[3]), "r"(b[0]), "r"(b[1]));
}
__device__ __forceinline__ void cpa16(uint32_t dst, const void* src){
    asm volatile("cp.async.cg.shared.global [%0], [%1], 16;"
                 :: "r"(dst), "l"(src) : "memory");
}
#define CP_COMMIT() asm volatile("cp.async.commit_group;" ::: "memory")
#define CP_WAIT1()  asm volatile("cp.async.wait_group 1;" ::: "memory")

// =================== bf16 mma.sync GEMM, tile 128x128, 4 warps =============
// C[r,c] = sum_k A[r,k]*W[c,k], bf16 K-major (row strides lda/ldw elements).
// 4 warps as 2m x 2n, warp tile 64x64, K chunks of 64, fp32 accum. 2 CTA/SM.
// Coalesced fill (4 lines/instr), early fill issue, fragment double-buffer.
// MODE 0: +bias[z*dB+c]       -> bf16 out   (q/k proj, z-stacked)
// MODE 1: expf(acc-xd[z*dB+r])/16 -> bf16   (features, z-stacked)
// MODE 2: acc/(Dv[z*dB+r]+eps)-> bf16 out   (y)
// MODE 3: +bias[c]+addsrc     -> f32 out    (final)
// MODE 4: plain               -> f32 out    (kptv partials; split-K)
// MODE 6: +bias[c]            -> f32 out    (v, K=1536 fused)
template<int MODE>
__global__ __launch_bounds__(128, 2) void gemm_bf(
    const bf16* __restrict__ A, const bf16* __restrict__ W, void* __restrict__ Cv,
    int K, int lda, int ldw, int ncols,
    const float* __restrict__ bias, const float* __restrict__ xd,
    const float* __restrict__ Dv, const float* __restrict__ addsrc,
    size_t aB, size_t wB, size_t cB, int dB, int splitk)
{
    extern __shared__ char smc[];
    const uint32_t sb = (uint32_t)__cvta_generic_to_shared(smc);
    const int tid = threadIdx.x, lane = tid & 31, wid = tid >> 5;
    const int z = blockIdx.z;
    const bf16* Ab = A;
    const bf16* Wb = W;
    size_t cOff;
    if (MODE == 4 && splitk > 1) {
        int b = z / splitk, sk = z - b*splitk;
        Ab += b*aB + (size_t)sk*K;
        Wb += b*wB + (size_t)sk*K;
        cOff = (size_t)z*cB;
    } else {
        Ab += (size_t)z*aB; Wb += (size_t)z*wB; cOff = (size_t)z*cB;
    }
    if (MODE == 0 || MODE == 6) bias += (size_t)z*dB;
    if (MODE == 1) xd += (size_t)z*dB;
    const int rowBase = blockIdx.x*128, colBase = blockIdx.y*128;

    // coalesced fill: octet o=tid>>3 covers rows {o, o+16,...}, lane c=tid&7 chunk c
    const int r0 = tid >> 3, cch = tid & 7;
    const bf16* gA = Ab + (size_t)(rowBase + r0)*lda + cch*8;
    const bf16* gB = Wb + (size_t)(colBase + r0)*ldw + cch*8;
    const size_t stepA = (size_t)16*lda;
    const size_t stepB = (size_t)16*ldw;
    const uint32_t sAd = sb + (uint32_t)r0*128u + (uint32_t)((cch ^ (r0 & 7)) << 4);
    const uint32_t sBd = sAd + 16384u;
    const int nCh = K / KCB;

    #define LOAD_STAGE(i) do {                                            \
        if ((i) < nCh) {                                                  \
            const uint32_t stg = ((i) % NSTAGE)*STG_B;                    \
            const bf16* pA = gA + (size_t)(i)*KCB;                        \
            const bf16* pB = gB + (size_t)(i)*KCB;                        \
            _Pragma("unroll")                                             \
            for (int j = 0; j < 8; j++) {                                 \
                cpa16(sAd + stg + (uint32_t)(j*2048), pA + (size_t)j*stepA); \
                cpa16(sBd + stg + (uint32_t)(j*2048), pB + (size_t)j*stepB); \
            }                                                             \
        }                                                                 \
        CP_COMMIT();                                                      \
    } while (0)

    LOAD_STAGE(0);
    LOAD_STAGE(1);

    const int wm = wid & 1, wn = wid >> 1;
    const int rq = lane >> 2;
    const int sw = lane & 7;
    const int lrow8 = (lane & 7) + ((lane >> 3) & 1) * 8;
    const int khalf = lane >> 4;
    uint32_t aOff[4], bOff[4];
    #pragma unroll
    for (int mi = 0; mi < 4; mi++)
        aOff[mi] = (uint32_t)(wm*64 + mi*16 + lrow8) * 128u;
    #pragma unroll
    for (int nb = 0; nb < 4; nb++)
        bOff[nb] = 16384u + (uint32_t)(wn*64 + nb*16 + lrow8) * 128u;

    float acc[4][8][4];
    #pragma unroll
    for (int mi = 0; mi < 4; mi++)
        #pragma unroll
        for (int ni = 0; ni < 8; ni++)
            #pragma unroll
            for (int t = 0; t < 4; t++) acc[mi][ni][t] = 0.f;

    #define LDFRAG(ksv, AF, BF) do {                                          \
        const uint32_t kq = (uint32_t)(((((ksv)*2) + khalf) ^ sw) << 4);      \
        _Pragma("unroll")                                                     \
        for (int mi = 0; mi < 4; mi++) ldsm4(AF[mi], sA + aOff[mi] + kq);     \
        _Pragma("unroll")                                                     \
        for (int nb = 0; nb < 4; nb++) {                                      \
            uint32_t m[4];                                                    \
            ldsm4(m, sA + bOff[nb] + kq);                                     \
            BF[2*nb  ][0] = m[0]; BF[2*nb+1][0] = m[1];                       \
            BF[2*nb  ][1] = m[2]; BF[2*nb+1][1] = m[3];                       \
        }                                                                     \
    } while (0)

    #define MMAALL(AF, BF) do {                                               \
        _Pragma("unroll")                                                     \
        for (int mi = 0; mi < 4; mi++)                                        \
            _Pragma("unroll")                                                 \
            for (int ni = 0; ni < 8; ni++)                                    \
                mma16(acc[mi][ni], AF[mi], BF[ni]);                           \
    } while (0)

    for (int i = 0; i < nCh; i++) {
        CP_WAIT1();
        __syncthreads();
        LOAD_STAGE(i + 2);                    // early issue: overlaps whole MMA block
        const uint32_t sA = sb + (i % NSTAGE)*STG_B;
        uint32_t afA[4][4], bfA[8][2], afB[4][4], bfB[8][2];
        LDFRAG(0, afA, bfA);
        LDFRAG(1, afB, bfB);
        MMAALL(afA, bfA);
        LDFRAG(2, afA, bfA);
        MMAALL(afB, bfB);
        LDFRAG(3, afB, bfB);
        MMAALL(afA, bfA);
        MMAALL(afB, bfB);
    }

    // ---------------- epilogue ---------------------------------------------
    bf16*  Cb = (bf16*)Cv + cOff;
    float* Cf = (float*)Cv + cOff;
    const int c2 = (lane & 3)*2;
    #pragma unroll
    for (int mi = 0; mi < 4; mi++) {
        const int r0e = rowBase + wm*64 + mi*16 + rq;
        const int r1e = r0e + 8;
        float e0 = 0.f, e1 = 0.f, d0 = 1.f, d1 = 1.f;
        if (MODE == 1) { e0 = xd[r0e]; e1 = xd[r1e]; }
        if (MODE == 2) {
            d0 = 1.f/(Dv[(size_t)z*dB + r0e] + 1e-8f);
            d1 = 1.f/(Dv[(size_t)z*dB + r1e] + 1e-8f);
        }
        #pragma unroll
        for (int ni = 0; ni < 8; ni++) {
            const int cc = colBase + wn*64 + ni*8 + c2;
            float t0 = acc[mi][ni][0], t1v = acc[mi][ni][1];
            float t2 = acc[mi][ni][2], t3  = acc[mi][ni][3];
            if (MODE == 0 || MODE == 6) {
                float2 bv = *reinterpret_cast<const float2*>(bias + cc);
                t0 += bv.x; t1v += bv.y; t2 += bv.x; t3 += bv.y;
            } else if (MODE == 1) {
                t0 = expf(t0 - e0)*0.0625f; t1v = expf(t1v - e0)*0.0625f;
                t2 = expf(t2 - e1)*0.0625f; t3  = expf(t3  - e1)*0.0625f;
            } else if (MODE == 2) {
                t0 *= d0; t1v *= d0; t2 *= d1; t3 *= d1;
            } else if (MODE == 3) {
                float2 bv = *reinterpret_cast<const float2*>(bias + cc);
                float2 s0 = *reinterpret_cast<const float2*>(addsrc + (size_t)r0e*ncols + cc);
                float2 s1 = *reinterpret_cast<const float2*>(addsrc + (size_t)r1e*ncols + cc);
                t0 += bv.x + s0.x; t1v += bv.y + s0.y;
                t2 += bv.x + s1.x; t3  += bv.y + s1.y;
            }
            if (MODE <= 2) {
                *reinterpret_cast<bf162*>(Cb + (size_t)r0e*ncols + cc) = __floats2bfloat162_rn(t0, t1v);
                *reinterpret_cast<bf162*>(Cb + (size_t)r1e*ncols + cc) = __floats2bfloat162_rn(t2, t3);
            } else {
                *reinterpret_cast<float2*>(Cf + (size_t)r0e*ncols + cc) = make_float2(t0, t1v);
                *reinterpret_cast<float2*>(Cf + (size_t)r1e*ncols + cc) = make_float2(t2, t3);
            }
        }
    }
    #undef LOAD_STAGE
    #undef LDFRAG
    #undef MMAALL
}

// ---------------- one fused weight-conversion kernel -----------------------
__global__ __launch_bounds__(256) void conv_all(
    const float* __restrict__ qw, const float* __restrict__ kw,
    const float* __restrict__ pw, const float* __restrict__ w,
    const float* __restrict__ vw,
    const float* __restrict__ qb, const float* __restrict__ kb,
    bf16* __restrict__ qkw, bf16* __restrict__ pwb, bf16* __restrict__ wb,
    bf16* __restrict__ vw1536, float* __restrict__ qkb)
{
    int i = blockIdx.x*256 + threadIdx.x;
    if (i < N1) {
        qkw[i] = __float2bfloat16_rn(qw[i]);
    } else if (i < 2*N1) {
        qkw[i] = __float2bfloat16_rn(kw[i - N1]);
    } else if (i < 3*N1) {
        int j = i - 2*N1; pwb[j] = __float2bfloat16_rn(pw[j]);
    } else if (i < 3*N1 + MF*EE) {
        int j = i - 3*N1; wb[j] = __float2bfloat16_rn(w[j]);
    } else if (i < 4*N1 + MF*EE) {
        int j = i - 3*N1 - MF*EE;
        int row = j >> 9, col = j & 511;
        float v = vw[j];
        bf16 hv = __float2bfloat16_rn(v);
        bf16 lv = __float2bfloat16_rn(v - __bfloat162float(hv));
        vw1536[(size_t)row*1536 + col]        = hv;   // pairs with xnh
        vw1536[(size_t)row*1536 + 512 + col]  = hv;   // pairs with xnl
        vw1536[(size_t)row*1536 + 1024 + col] = lv;   // pairs with xnh (dup)
    } else if (i < 4*N1 + MF*EE + 2*EE) {
        int j = i - 4*N1 - MF*EE;
        qkb[j] = (j < EE) ? qb[j] : kb[j - EE];
    }
}

// ---------------- LayerNorm -> [hi | lo | hi] bf16 (stride 1536) -----------
__global__ __launch_bounds__(128) void ln_kernel(
    const float* __restrict__ x, const float* __restrict__ gamma,
    const float* __restrict__ beta, bf16* __restrict__ xhl)
{
    int row = blockIdx.x;
    const float4* xr = reinterpret_cast<const float4*>(x + (size_t)row*EE);
    int t = threadIdx.x;
    float4 v = xr[t];
    float s  = v.x+v.y+v.z+v.w;
    float s2 = v.x*v.x+v.y*v.y+v.z*v.z+v.w*v.w;
    #pragma unroll
    for (int o=16;o>0;o>>=1){
        s  += __shfl_xor_sync(0xffffffffu, s,  o);
        s2 += __shfl_xor_sync(0xffffffffu, s2, o);
    }
    __shared__ float rs[4], rs2[4];
    int wid = t>>5, lane = t&31;
    if (lane==0){ rs[wid]=s; rs2[wid]=s2; }
    __syncthreads();
    s  = rs[0]+rs[1]+rs[2]+rs[3];
    s2 = rs2[0]+rs2[1]+rs2[2]+rs2[3];
    float mu  = s * (1.f/EE);
    float var = s2*(1.f/EE) - mu*mu;
    float inv = rsqrtf(var + 1e-5f);
    float4 g  = reinterpret_cast<const float4*>(gamma)[t];
    float4 bt = reinterpret_cast<const float4*>(beta)[t];
    float o[4];
    o[0] = (v.x-mu)*inv*g.x + bt.x;
    o[1] = (v.y-mu)*inv*g.y + bt.y;
    o[2] = (v.z-mu)*inv*g.z + bt.z;
    o[3] = (v.w-mu)*inv*g.w + bt.w;
    bf16 h[4]; float l[4];
    #pragma unroll
    for (int j=0;j<4;j++){ h[j]=__float2bfloat16_rn(o[j]); l[j]=o[j]-__bfloat162float(h[j]); }
    bf162 hp0(h[0], h[1]), hp1(h[2], h[3]);
    bf16* base = xhl + (size_t)row*1536;
    reinterpret_cast<bf162*>(base + t*4)[0] = hp0;
    reinterpret_cast<bf162*>(base + t*4)[1] = hp1;
    reinterpret_cast<bf162*>(base + 512 + t*4)[0] = __floats2bfloat162_rn(l[0], l[1]);
    reinterpret_cast<bf162*>(base + 512 + t*4)[1] = __floats2bfloat162_rn(l[2], l[3]);
    reinterpret_cast<bf162*>(base + 1024 + t*4)[0] = hp0;
    reinterpret_cast<bf162*>(base + 1024 + t*4)[1] = hp1;
}

// ---------------- 0.5*||row||^2 of bf16 q,k --------------------------------
__device__ __forceinline__ float sumsq8(uint4 u){
    float s = 0.f;
    uint32_t a[4] = {u.x, u.y, u.z, u.w};
    #pragma unroll
    for (int j=0;j<4;j++){
        float2 f = __bfloat1622float2(*reinterpret_cast<bf162*>(&a[j]));
        s += f.x*f.x + f.y*f.y;
    }
    return s;
}
__global__ __launch_bounds__(256) void xd_kernel(
    const bf16* __restrict__ q, const bf16* __restrict__ k,
    float* __restrict__ xdq, float* __restrict__ xdk)
{
    int row  = blockIdx.x*8 + (threadIdx.x>>5);
    int lane = threadIdx.x&31;
    const uint4* qr = reinterpret_cast<const uint4*>(q + (size_t)row*EE);
    const uint4* kr = reinterpret_cast<const uint4*>(k + (size_t)row*EE);
    float sq=0.f, sk=0.f;
    #pragma unroll
    for (int j=0;j<2;j++){
        sq += sumsq8(qr[lane + j*32]);
        sk += sumsq8(kr[lane + j*32]);
    }
    #pragma unroll
    for (int o=16;o>0;o>>=1){
        sq += __shfl_xor_sync(0xffffffffu, sq, o);
        sk += __shfl_xor_sync(0xffffffffu, sk, o);
    }
    if (lane==0){ xdq[row]=0.5f*sq; xdk[row]=0.5f*sk; }
}

// ---------------- column sums of kp (bf16) per batch -----------------------
__global__ __launch_bounds__(256) void ksum_kernel(
    const bf16* __restrict__ kp, float* __restrict__ out)
{
    int b = blockIdx.x, m0 = blockIdx.y*64;
    int tx = threadIdx.x & 63, ty = threadIdx.x >> 6;
    const bf16* base = kp + (size_t)b*SS*MF + m0 + tx;
    float s=0.f;
    for (int srow=ty; srow<SS; srow+=4) s += __bfloat162float(base[(size_t)srow*MF]);
    __shared__ float red[4][64];
    red[ty][tx]=s;
    __syncthreads();
    if (ty==0) out[b*MF+m0+tx] = red[0][tx]+red[1][tx]+red[2][tx]+red[3][tx];
}

// ---------------- batched 2D transpose with dtype convert ------------------
__device__ __forceinline__ float ldf(const float* p){ return *p; }
__device__ __forceinline__ float ldf(const bf16* p){ return __bfloat162float(*p); }
__device__ __forceinline__ void stf(float* p, float v){ *p = v; }
__device__ __forceinline__ void stf(bf16* p, float v){ *p = __float2bfloat16_rn(v); }

template<typename TI, typename TO>
__global__ __launch_bounds__(256) void transpose_t(
    const TI* __restrict__ in, TO* __restrict__ out, int R, int Cc)
{
    __shared__ float t[32][33];
    int z = blockIdx.z;
    in  += (size_t)z*R*Cc;
    out += (size_t)z*R*Cc;
    int tx = threadIdx.x & 31, ty = threadIdx.x >> 5;
    int x  = blockIdx.x*32 + tx;
    int y0 = blockIdx.y*32;
    #pragma unroll
    for (int j=0;j<4;j++)
        t[ty + j*8][tx] = ldf(in + (size_t)(y0 + ty + j*8)*Cc + x);
    __syncthreads();
    int xo = y0 + tx;
    int c0 = blockIdx.x*32;
    #pragma unroll
    for (int j=0;j<4;j++)
        stf(out + (size_t)(c0 + ty + j*8)*R + xo, t[tx][ty + j*8]);
}

// ---------------- reduce split-K partials -> bf16 --------------------------
__global__ __launch_bounds__(256) void reduce_kptv(
    const float* __restrict__ p, bf16* __restrict__ o)
{
    const size_t EM = (size_t)EE*MF;
    size_t i = (size_t)blockIdx.x*256 + threadIdx.x;
    int b = blockIdx.y;
    const float* pb = p + (size_t)b*SPLITK*EM + i;
    float s = 0.f;
    #pragma unroll
    for (int sk=0; sk<SPLITK; sk++) s += pb[(size_t)sk*EM];
    o[(size_t)b*EM + i] = __float2bfloat16_rn(s);
}

// ---------------- D[r] = qp[r,:] . ksum[b,:] -------------------------------
__global__ __launch_bounds__(256) void d_kernel(
    const bf16* __restrict__ qp, const float* __restrict__ ks,
    float* __restrict__ D)
{
    int row  = blockIdx.x*8 + (threadIdx.x>>5);
    int lane = threadIdx.x&31;
    int b = row >> 12;
    uint4 u = *reinterpret_cast<const uint4*>(qp + (size_t)row*MF + lane*8);
    float4 k0 = *reinterpret_cast<const float4*>(ks + b*MF + lane*8);
    float4 k1 = *reinterpret_cast<const float4*>(ks + b*MF + lane*8 + 4);
    uint32_t a[4] = {u.x, u.y, u.z, u.w};
    float kk[8] = {k0.x,k0.y,k0.z,k0.w,k1.x,k1.y,k1.z,k1.w};
    float s=0.f;
    #pragma unroll
    for (int j=0;j<4;j++){
        float2 f = __bfloat1622float2(*reinterpret_cast<bf162*>(&a[j]));
        s += f.x*kk[2*j] + f.y*kk[2*j+1];
    }
    #pragma unroll
    for (int o=16;o>0;o>>=1) s += __shfl_xor_sync(0xffffffffu, s, o);
    if (lane==0) D[row]=s;
}

// ---------------- launch ---------------------------------------------------
extern "C" void kernel_launch(void* const* d_in, const int* in_sizes, int n_in,
                              void* d_out, int out_size)
{
    const float* x     = (const float*)d_in[0];
    const float* qw    = (const float*)d_in[1];
    const float* qb    = (const float*)d_in[2];
    const float* kw    = (const float*)d_in[3];
    const float* kb    = (const float*)d_in[4];
    const float* vw    = (const float*)d_in[5];
    const float* vb    = (const float*)d_in[6];
    const float* pw    = (const float*)d_in[7];
    const float* pb    = (const float*)d_in[8];
    const float* gamma = (const float*)d_in[9];
    const float* beta  = (const float*)d_in[10];
    const float* w     = (const float*)d_in[11];
    float* out = (float*)d_out;

    bf16 *xhl,*qk,*qkp,*ybf,*vtb,*kptb,*kptvb,*qkw,*pwb,*wb,*vw1536;
    float *v,*xd2,*D,*ks,*kptvp,*qkb;
    cudaGetSymbolAddress((void**)&xhl,   g_xhl);
    cudaGetSymbolAddress((void**)&qk,    g_qk);
    cudaGetSymbolAddress((void**)&qkp,   g_qkp);
    cudaGetSymbolAddress((void**)&ybf,   g_yb);
    cudaGetSymbolAddress((void**)&vtb,   g_vtb);
    cudaGetSymbolAddress((void**)&kptb,  g_kptb);
    cudaGetSymbolAddress((void**)&kptvb, g_kptvb);
    cudaGetSymbolAddress((void**)&qkw,   g_qkw);
    cudaGetSymbolAddress((void**)&pwb,   g_pwb);
    cudaGetSymbolAddress((void**)&wb,    g_wb);
    cudaGetSymbolAddress((void**)&vw1536,g_vw1536);
    cudaGetSymbolAddress((void**)&v,     g_v);
    cudaGetSymbolAddress((void**)&xd2,   g_xd2);
    cudaGetSymbolAddress((void**)&D,     g_D);
    cudaGetSymbolAddress((void**)&ks,    g_ks);
    cudaGetSymbolAddress((void**)&kptvp, g_kptvp);
    cudaGetSymbolAddress((void**)&qkb,   g_qkb);

    cudaFuncSetAttribute(gemm_bf<0>, cudaFuncAttributeMaxDynamicSharedMemorySize, SMEM_B);
    cudaFuncSetAttribute(gemm_bf<1>, cudaFuncAttributeMaxDynamicSharedMemorySize, SMEM_B);
    cudaFuncSetAttribute(gemm_bf<2>, cudaFuncAttributeMaxDynamicSharedMemorySize, SMEM_B);
    cudaFuncSetAttribute(gemm_bf<3>, cudaFuncAttributeMaxDynamicSharedMemorySize, SMEM_B);
    cudaFuncSetAttribute(gemm_bf<4>, cudaFuncAttributeMaxDynamicSharedMemorySize, SMEM_B);
    cudaFuncSetAttribute(gemm_bf<6>, cudaFuncAttributeMaxDynamicSharedMemorySize, SMEM_B);

    dim3 blk(256);
    dim3 gblk(128);

    // 1) weight conversions (single launch)
    {
        int total = 4*N1 + MF*EE + 2*EE;
        conv_all<<<(total+255)/256,blk>>>(qw, kw, pw, w, vw, qb, kb,
                                          qkw, pwb, wb, vw1536, qkb);
    }

    // 2) LayerNorm -> xhl = [hi|lo|hi], row stride 1536
    ln_kernel<<<NR,128>>>(x, gamma, beta, xhl);

    // 3) q+k projections in one z-stacked launch (bf16 out)
    gemm_bf<0><<<dim3(NR/128, EE/128, 2),gblk,SMEM_B>>>(
        xhl, qkw, qk, EE, 3*EE, EE, EE, qkb, nullptr, nullptr, nullptr,
        0, (size_t)N1, (size_t)NR*EE, EE, 1);

    // 4) v in ONE fused K=1536 GEMM: xnh@vwh + xnl@vwh + xnh@vwl + vb (f32)
    gemm_bf<6><<<dim3(NR/128, EE/128, 1),gblk,SMEM_B>>>(
        xhl, vw1536, v, 3*EE, 3*EE, 3*EE, EE, vb, nullptr, nullptr, nullptr,
        0, 0, 0, 0, 1);

    // 5) row half-norms from bf16 q,k (stacked)
    xd_kernel<<<NR/8,256>>>(qk, qk + (size_t)NR*EE, xd2, xd2 + NR);

    // 6) features in one z-stacked launch (exp epilogue, bf16 out)
    gemm_bf<1><<<dim3(NR/128, MF/128, 2),gblk,SMEM_B>>>(
        qk, wb, qkp, EE, EE, EE, MF, nullptr, xd2, nullptr, nullptr,
        (size_t)NR*EE, 0, (size_t)NR*MF, NR, 1);

    // 7) ksum[b,m] from kp
    ksum_kernel<<<dim3(BB, MF/64),blk>>>(qkp + (size_t)NR*MF, ks);

    // 8) transposes: vtb[b][E][S] (f32->bf16), kptb[b][M][S] (bf16->bf16)
    transpose_t<float,bf16><<<dim3(EE/32, SS/32, BB),blk>>>(v, vtb, SS, EE);
    transpose_t<bf16,bf16> <<<dim3(MF/32, SS/32, BB),blk>>>(qkp + (size_t)NR*MF, kptb, SS, MF);

    // 9) kptv split-K partials (f32), reduce -> bf16
    gemm_bf<4><<<dim3(EE/128, MF/128, BB*SPLITK),gblk,SMEM_B>>>(
        vtb, kptb, kptvp, SS/SPLITK, SS, SS, MF, nullptr, nullptr, nullptr, nullptr,
        (size_t)EE*SS, (size_t)MF*SS, (size_t)EE*MF, 0, SPLITK);
    reduce_kptv<<<dim3((EE*MF)/256, BB),blk>>>(kptvp, kptvb);

    // 10) D[r]
    d_kernel<<<NR/8,256>>>(qkp, ks, D);

    // 11) y[b,s,e] = (qp @ kptv^T)/(D+eps), bf16 out
    gemm_bf<2><<<dim3(SS/128, EE/128, BB),gblk,SMEM_B>>>(
        qkp, kptvb, ybf, MF, MF, MF, EE, nullptr, nullptr, D, nullptr,
        (size_t)SS*MF, (size_t)EE*MF, (size_t)SS*EE, SS, 1);

    // 12) out = v + y @ pw^T + pb   (f32 out)
    gemm_bf<3><<<dim3(NR/128, EE/128, 1),gblk,SMEM_B>>>(
        ybf, pwb, out, EE, EE, EE, EE, pb, nullptr, nullptr, v, 0, 0, 0, 0, 1);
}

// round 12
// speedup vs baseline: 1.9498x; 1.0782x over previous
#include <cuda_runtime.h>
#include <cuda_bf16.h>
#include <math.h>
#include <stdint.h>

#define BB 8
#define SS 4096
#define NR (BB*SS)      // 32768 rows
#define EE 512
#define MF 256
#define SPLITK 8
#define NSTAGE 3
#define KCB 64                      // k elements (bf16) per chunk = 128B rows
#define STG_B 32768                 // bytes per stage: A 16KB + B 16KB
#define SMEM_B (NSTAGE*STG_B)       // 96KB
#define N1 (EE*EE)

typedef __nv_bfloat16 bf16;
typedef __nv_bfloat162 bf162;

// ---------------- scratch (device globals; no allocation allowed) ----------
__device__ bf16  g_xhl [(size_t)NR*3*EE];  // [row][0:512]=hi, [512:1024]=lo, [1024:1536]=hi
__device__ bf16  g_qk  [(size_t)2*NR*EE];  // stacked q, k (bf16)
__device__ bf16  g_qkp [(size_t)2*NR*MF];  // stacked qp, kp (bf16)
__device__ bf16  g_G   [(size_t)BB*EE*MF]; // folded pw@kptv' [b][C=512][M=256]
__device__ bf16  g_vtb [(size_t)NR*EE];    // [b][E][S]
__device__ bf16  g_kptb[(size_t)NR*MF];    // [b][M][S]
__device__ float g_v   [(size_t)NR*EE];
__device__ float g_xd2 [2*NR];             // stacked xdq, xdk
__device__ float g_D  [NR];
__device__ float g_ks [BB*MF];
__device__ float g_kptvp[(size_t)SPLITK*BB*EE*MF];
__device__ bf16  g_kptvb[(size_t)BB*MF*EE]; // kptv' [b][M][E] bf16
__device__ bf16  g_qkw[2*N1];              // stacked qw, kw (bf16)
__device__ bf16  g_pwb[N1];
__device__ bf16  g_wb [MF*EE];
__device__ bf16  g_vw1536[EE*3*EE];        // [c][0:512]=vwh, [512:1024]=vwh, [1024:1536]=vwl
__device__ float g_qkb[2*EE];              // stacked qb, kb

// =================== portable tensor-core helpers (sm_80+) =================
__device__ __forceinline__ void ldsm4(uint32_t* r, uint32_t addr){
    asm volatile("ldmatrix.sync.aligned.m8n8.x4.shared.b16 {%0,%1,%2,%3}, [%4];"
        : "=r"(r[0]), "=r"(r[1]), "=r"(r[2]), "=r"(r[3]) : "r"(addr));
}
__device__ __forceinline__ void mma16(float* d, const uint32_t* a, const uint32_t* b){
    asm volatile("mma.sync.aligned.m16n8k16.row.col.f32.bf16.bf16.f32 "
        "{%0,%1,%2,%3}, {%4,%5,%6,%7}, {%8,%9}, {%0,%1,%2,%3};"
        : "+f"(d[0]), "+f"(d[1]), "+f"(d[2]), "+f"(d[3])
        : "r"(a[0]), "r"(a[1]), "r"(a[2]), "r"(a[3]), "r"(b[0]), "r"(b[1]));
}
__device__ __forceinline__ void cpa16(uint32_t dst, const void* src){
    asm volatile("cp.async.cg.shared.global [%0], [%1], 16;"
                 :: "r"(dst), "l"(src) : "memory");
}
#define CP_COMMIT() asm volatile("cp.async.commit_group;" ::: "memory")
#define CP_WAIT1()  asm volatile("cp.async.wait_group 1;" ::: "memory")

// =================== bf16 mma.sync GEMM, tile 128x128, 4 warps =============
// C[r,c] = sum_k A[r,k]*W[c,k], bf16 K-major (row strides lda/ldw elements).
// 4 warps as 2m x 2n, warp tile 64x64, K chunks of 64, fp32 accum. 2 CTA/SM.
// Coalesced fill (4 lines/instr), early fill issue, fragment double-buffer.
// MODE 0: +bias[z*dB+c]           -> bf16 out  (q/k proj, z-stacked)
// MODE 1: expf(acc-xd[z*dB+r])/16 -> bf16 out  (features, z-stacked)
// MODE 4: plain                   -> f32 out   (kptv' partials; split-K)
// MODE 5: plain                   -> bf16 out  (G = pw @ kptv')
// MODE 6: +bias[c]                -> f32 out   (v, K=1536 fused)
// MODE 7: acc/(Dv[z*dB+r]+eps) + bias[c] + addsrc[z][r][c] -> f32 (final)
template<int MODE>
__global__ __launch_bounds__(128, 2) void gemm_bf(
    const bf16* __restrict__ A, const bf16* __restrict__ W, void* __restrict__ Cv,
    int K, int lda, int ldw, int ncols,
    const float* __restrict__ bias, const float* __restrict__ xd,
    const float* __restrict__ Dv, const float* __restrict__ addsrc,
    size_t aB, size_t wB, size_t cB, int dB, int splitk)
{
    extern __shared__ char smc[];
    const uint32_t sb = (uint32_t)__cvta_generic_to_shared(smc);
    const int tid = threadIdx.x, lane = tid & 31, wid = tid >> 5;
    const int z = blockIdx.z;
    const bf16* Ab = A;
    const bf16* Wb = W;
    size_t cOff;
    if (MODE == 4 && splitk > 1) {
        int b = z / splitk, sk = z - b*splitk;
        Ab += b*aB + (size_t)sk*K;
        Wb += b*wB + (size_t)sk*K;
        cOff = (size_t)z*cB;
    } else {
        Ab += (size_t)z*aB; Wb += (size_t)z*wB; cOff = (size_t)z*cB;
    }
    if (MODE == 0 || MODE == 6) bias += (size_t)z*dB;
    if (MODE == 1) xd += (size_t)z*dB;
    if (MODE == 7) addsrc += cOff;
    const int rowBase = blockIdx.x*128, colBase = blockIdx.y*128;

    // coalesced fill: octet o=tid>>3 covers rows {o, o+16,...}, lane c=tid&7 chunk c
    const int r0 = tid >> 3, cch = tid & 7;
    const bf16* gA = Ab + (size_t)(rowBase + r0)*lda + cch*8;
    const bf16* gB = Wb + (size_t)(colBase + r0)*ldw + cch*8;
    const size_t stepA = (size_t)16*lda;
    const size_t stepB = (size_t)16*ldw;
    const uint32_t sAd = sb + (uint32_t)r0*128u + (uint32_t)((cch ^ (r0 & 7)) << 4);
    const uint32_t sBd = sAd + 16384u;
    const int nCh = K / KCB;

    #define LOAD_STAGE(i) do {                                            \
        if ((i) < nCh) {                                                  \
            const uint32_t stg = ((i) % NSTAGE)*STG_B;                    \
            const bf16* pA = gA + (size_t)(i)*KCB;                        \
            const bf16* pB = gB + (size_t)(i)*KCB;                        \
            _Pragma("unroll")                                             \
            for (int j = 0; j < 8; j++) {                                 \
                cpa16(sAd + stg + (uint32_t)(j*2048), pA + (size_t)j*stepA); \
                cpa16(sBd + stg + (uint32_t)(j*2048), pB + (size_t)j*stepB); \
            }                                                             \
        }                                                                 \
        CP_COMMIT();                                                      \
    } while (0)

    LOAD_STAGE(0);
    LOAD_STAGE(1);

    const int wm = wid & 1, wn = wid >> 1;
    const int rq = lane >> 2;
    const int sw = lane & 7;
    const int lrow8 = (lane & 7) + ((lane >> 3) & 1) * 8;
    const int khalf = lane >> 4;
    uint32_t aOff[4], bOff[4];
    #pragma unroll
    for (int mi = 0; mi < 4; mi++)
        aOff[mi] = (uint32_t)(wm*64 + mi*16 + lrow8) * 128u;
    #pragma unroll
    for (int nb = 0; nb < 4; nb++)
        bOff[nb] = 16384u + (uint32_t)(wn*64 + nb*16 + lrow8) * 128u;

    float acc[4][8][4];
    #pragma unroll
    for (int mi = 0; mi < 4; mi++)
        #pragma unroll
        for (int ni = 0; ni < 8; ni++)
            #pragma unroll
            for (int t = 0; t < 4; t++) acc[mi][ni][t] = 0.f;

    #define LDFRAG(ksv, AF, BF) do {                                          \
        const uint32_t kq = (uint32_t)(((((ksv)*2) + khalf) ^ sw) << 4);      \
        _Pragma("unroll")                                                     \
        for (int mi = 0; mi < 4; mi++) ldsm4(AF[mi], sA + aOff[mi] + kq);     \
        _Pragma("unroll")                                                     \
        for (int nb = 0; nb < 4; nb++) {                                      \
            uint32_t m[4];                                                    \
            ldsm4(m, sA + bOff[nb] + kq);                                     \
            BF[2*nb  ][0] = m[0]; BF[2*nb+1][0] = m[1];                       \
            BF[2*nb  ][1] = m[2]; BF[2*nb+1][1] = m[3];                       \
        }                                                                     \
    } while (0)

    #define MMAALL(AF, BF) do {                                               \
        _Pragma("unroll")                                                     \
        for (int mi = 0; mi < 4; mi++)                                        \
            _Pragma("unroll")                                                 \
            for (int ni = 0; ni < 8; ni++)                                    \
                mma16(acc[mi][ni], AF[mi], BF[ni]);                           \
    } while (0)

    for (int i = 0; i < nCh; i++) {
        CP_WAIT1();
        __syncthreads();
        LOAD_STAGE(i + 2);                    // early issue: overlaps whole MMA block
        const uint32_t sA = sb + (i % NSTAGE)*STG_B;
        uint32_t afA[4][4], bfA[8][2], afB[4][4], bfB[8][2];
        LDFRAG(0, afA, bfA);
        LDFRAG(1, afB, bfB);
        MMAALL(afA, bfA);
        LDFRAG(2, afA, bfA);
        MMAALL(afB, bfB);
        LDFRAG(3, afB, bfB);
        MMAALL(afA, bfA);
        MMAALL(afB, bfB);
    }

    // ---------------- epilogue ---------------------------------------------
    constexpr bool BF16OUT = (MODE <= 1 || MODE == 5);
    bf16*  Cb = (bf16*)Cv + cOff;
    float* Cf = (float*)Cv + cOff;
    const int c2 = (lane & 3)*2;
    #pragma unroll
    for (int mi = 0; mi < 4; mi++) {
        const int r0e = rowBase + wm*64 + mi*16 + rq;
        const int r1e = r0e + 8;
        float e0 = 0.f, e1 = 0.f, d0 = 1.f, d1 = 1.f;
        if (MODE == 1) { e0 = xd[r0e]; e1 = xd[r1e]; }
        if (MODE == 7) {
            d0 = 1.f/(Dv[(size_t)z*dB + r0e] + 1e-8f);
            d1 = 1.f/(Dv[(size_t)z*dB + r1e] + 1e-8f);
        }
        #pragma unroll
        for (int ni = 0; ni < 8; ni++) {
            const int cc = colBase + wn*64 + ni*8 + c2;
            float t0 = acc[mi][ni][0], t1v = acc[mi][ni][1];
            float t2 = acc[mi][ni][2], t3  = acc[mi][ni][3];
            if (MODE == 0 || MODE == 6) {
                float2 bv = *reinterpret_cast<const float2*>(bias + cc);
                t0 += bv.x; t1v += bv.y; t2 += bv.x; t3 += bv.y;
            } else if (MODE == 1) {
                t0 = expf(t0 - e0)*0.0625f; t1v = expf(t1v - e0)*0.0625f;
                t2 = expf(t2 - e1)*0.0625f; t3  = expf(t3  - e1)*0.0625f;
            } else if (MODE == 7) {
                float2 bv = *reinterpret_cast<const float2*>(bias + cc);
                float2 s0 = *reinterpret_cast<const float2*>(addsrc + (size_t)r0e*ncols + cc);
                float2 s1 = *reinterpret_cast<const float2*>(addsrc + (size_t)r1e*ncols + cc);
                t0  = t0 *d0 + bv.x + s0.x; t1v = t1v*d0 + bv.y + s0.y;
                t2  = t2 *d1 + bv.x + s1.x; t3  = t3 *d1 + bv.y + s1.y;
            }
            if (BF16OUT) {
                *reinterpret_cast<bf162*>(Cb + (size_t)r0e*ncols + cc) = __floats2bfloat162_rn(t0, t1v);
                *reinterpret_cast<bf162*>(Cb + (size_t)r1e*ncols + cc) = __floats2bfloat162_rn(t2, t3);
            } else {
                *reinterpret_cast<float2*>(Cf + (size_t)r0e*ncols + cc) = make_float2(t0, t1v);
                *reinterpret_cast<float2*>(Cf + (size_t)r1e*ncols + cc) = make_float2(t2, t3);
            }
        }
    }
    #undef LOAD_STAGE
    #undef LDFRAG
    #undef MMAALL
}

// ---------------- one fused weight-conversion kernel -----------------------
__global__ __launch_bounds__(256) void conv_all(
    const float* __restrict__ qw, const float* __restrict__ kw,
    const float* __restrict__ pw, const float* __restrict__ w,
    const float* __restrict__ vw,
    const float* __restrict__ qb, const float* __restrict__ kb,
    bf16* __restrict__ qkw, bf16* __restrict__ pwb, bf16* __restrict__ wb,
    bf16* __restrict__ vw1536, float* __restrict__ qkb)
{
    int i = blockIdx.x*256 + threadIdx.x;
    if (i < N1) {
        qkw[i] = __float2bfloat16_rn(qw[i]);
    } else if (i < 2*N1) {
        qkw[i] = __float2bfloat16_rn(kw[i - N1]);
    } else if (i < 3*N1) {
        int j = i - 2*N1; pwb[j] = __float2bfloat16_rn(pw[j]);
    } else if (i < 3*N1 + MF*EE) {
        int j = i - 3*N1; wb[j] = __float2bfloat16_rn(w[j]);
    } else if (i < 4*N1 + MF*EE) {
        int j = i - 3*N1 - MF*EE;
        int row = j >> 9, col = j & 511;
        float v = vw[j];
        bf16 hv = __float2bfloat16_rn(v);
        bf16 lv = __float2bfloat16_rn(v - __bfloat162float(hv));
        vw1536[(size_t)row*1536 + col]        = hv;   // pairs with xnh
        vw1536[(size_t)row*1536 + 512 + col]  = hv;   // pairs with xnl
        vw1536[(size_t)row*1536 + 1024 + col] = lv;   // pairs with xnh (dup)
    } else if (i < 4*N1 + MF*EE + 2*EE) {
        int j = i - 4*N1 - MF*EE;
        qkb[j] = (j < EE) ? qb[j] : kb[j - EE];
    }
}

// ---------------- LayerNorm -> [hi | lo | hi] bf16 (stride 1536) -----------
__global__ __launch_bounds__(128) void ln_kernel(
    const float* __restrict__ x, const float* __restrict__ gamma,
    const float* __restrict__ beta, bf16* __restrict__ xhl)
{
    int row = blockIdx.x;
    const float4* xr = reinterpret_cast<const float4*>(x + (size_t)row*EE);
    int t = threadIdx.x;
    float4 v = xr[t];
    float s  = v.x+v.y+v.z+v.w;
    float s2 = v.x*v.x+v.y*v.y+v.z*v.z+v.w*v.w;
    #pragma unroll
    for (int o=16;o>0;o>>=1){
        s  += __shfl_xor_sync(0xffffffffu, s,  o);
        s2 += __shfl_xor_sync(0xffffffffu, s2, o);
    }
    __shared__ float rs[4], rs2[4];
    int wid = t>>5, lane = t&31;
    if (lane==0){ rs[wid]=s; rs2[wid]=s2; }
    __syncthreads();
    s  = rs[0]+rs[1]+rs[2]+rs[3];
    s2 = rs2[0]+rs2[1]+rs2[2]+rs2[3];
    float mu  = s * (1.f/EE);
    float var = s2*(1.f/EE) - mu*mu;
    float inv = rsqrtf(var + 1e-5f);
    float4 g  = reinterpret_cast<const float4*>(gamma)[t];
    float4 bt = reinterpret_cast<const float4*>(beta)[t];
    float o[4];
    o[0] = (v.x-mu)*inv*g.x + bt.x;
    o[1] = (v.y-mu)*inv*g.y + bt.y;
    o[2] = (v.z-mu)*inv*g.z + bt.z;
    o[3] = (v.w-mu)*inv*g.w + bt.w;
    bf16 h[4]; float l[4];
    #pragma unroll
    for (int j=0;j<4;j++){ h[j]=__float2bfloat16_rn(o[j]); l[j]=o[j]-__bfloat162float(h[j]); }
    bf162 hp0(h[0], h[1]), hp1(h[2], h[3]);
    bf16* base = xhl + (size_t)row*1536;
    reinterpret_cast<bf162*>(base + t*4)[0] = hp0;
    reinterpret_cast<bf162*>(base + t*4)[1] = hp1;
    reinterpret_cast<bf162*>(base + 512 + t*4)[0] = __floats2bfloat162_rn(l[0], l[1]);
    reinterpret_cast<bf162*>(base + 512 + t*4)[1] = __floats2bfloat162_rn(l[2], l[3]);
    reinterpret_cast<bf162*>(base + 1024 + t*4)[0] = hp0;
    reinterpret_cast<bf162*>(base + 1024 + t*4)[1] = hp1;
}

// ---------------- 0.5*||row||^2 of bf16 q,k --------------------------------
__device__ __forceinline__ float sumsq8(uint4 u){
    float s = 0.f;
    uint32_t a[4] = {u.x, u.y, u.z, u.w};
    #pragma unroll
    for (int j=0;j<4;j++){
        float2 f = __bfloat1622float2(*reinterpret_cast<bf162*>(&a[j]));
        s += f.x*f.x + f.y*f.y;
    }
    return s;
}
__global__ __launch_bounds__(256) void xd_kernel(
    const bf16* __restrict__ q, const bf16* __restrict__ k,
    float* __restrict__ xdq, float* __restrict__ xdk)
{
    int row  = blockIdx.x*8 + (threadIdx.x>>5);
    int lane = threadIdx.x&31;
    const uint4* qr = reinterpret_cast<const uint4*>(q + (size_t)row*EE);
    const uint4* kr = reinterpret_cast<const uint4*>(k + (size_t)row*EE);
    float sq=0.f, sk=0.f;
    #pragma unroll
    for (int j=0;j<2;j++){
        sq += sumsq8(qr[lane + j*32]);
        sk += sumsq8(kr[lane + j*32]);
    }
    #pragma unroll
    for (int o=16;o>0;o>>=1){
        sq += __shfl_xor_sync(0xffffffffu, sq, o);
        sk += __shfl_xor_sync(0xffffffffu, sk, o);
    }
    if (lane==0){ xdq[row]=0.5f*sq; xdk[row]=0.5f*sk; }
}

// ---------------- column sums of kp (bf16) per batch -----------------------
__global__ __launch_bounds__(256) void ksum_kernel(
    const bf16* __restrict__ kp, float* __restrict__ out)
{
    int b = blockIdx.x, m0 = blockIdx.y*64;
    int tx = threadIdx.x & 63, ty = threadIdx.x >> 6;
    const bf16* base = kp + (size_t)b*SS*MF + m0 + tx;
    float s=0.f;
    for (int srow=ty; srow<SS; srow+=4) s += __bfloat162float(base[(size_t)srow*MF]);
    __shared__ float red[4][64];
    red[ty][tx]=s;
    __syncthreads();
    if (ty==0) out[b*MF+m0+tx] = red[0][tx]+red[1][tx]+red[2][tx]+red[3][tx];
}

// ---------------- batched 2D transpose with dtype convert ------------------
__device__ __forceinline__ float ldf(const float* p){ return *p; }
__device__ __forceinline__ float ldf(const bf16* p){ return __bfloat162float(*p); }
__device__ __forceinline__ void stf(float* p, float v){ *p = v; }
__device__ __forceinline__ void stf(bf16* p, float v){ *p = __float2bfloat16_rn(v); }

template<typename TI, typename TO>
__global__ __launch_bounds__(256) void transpose_t(
    const TI* __restrict__ in, TO* __restrict__ out, int R, int Cc)
{
    __shared__ float t[32][33];
    int z = blockIdx.z;
    in  += (size_t)z*R*Cc;
    out += (size_t)z*R*Cc;
    int tx = threadIdx.x & 31, ty = threadIdx.x >> 5;
    int x  = blockIdx.x*32 + tx;
    int y0 = blockIdx.y*32;
    #pragma unroll
    for (int j=0;j<4;j++)
        t[ty + j*8][tx] = ldf(in + (size_t)(y0 + ty + j*8)*Cc + x);
    __syncthreads();
    int xo = y0 + tx;
    int c0 = blockIdx.x*32;
    #pragma unroll
    for (int j=0;j<4;j++)
        stf(out + (size_t)(c0 + ty + j*8)*R + xo, t[tx][ty + j*8]);
}

// ---------------- reduce split-K partials -> bf16 --------------------------
__global__ __launch_bounds__(256) void reduce_kptv(
    const float* __restrict__ p, bf16* __restrict__ o)
{
    const size_t EM = (size_t)EE*MF;
    size_t i = (size_t)blockIdx.x*256 + threadIdx.x;
    int b = blockIdx.y;
    const float* pb = p + (size_t)b*SPLITK*EM + i;
    float s = 0.f;
    #pragma unroll
    for (int sk=0; sk<SPLITK; sk++) s += pb[(size_t)sk*EM];
    o[(size_t)b*EM + i] = __float2bfloat16_rn(s);
}

// ---------------- D[r] = qp[r,:] . ksum[b,:] -------------------------------
__global__ __launch_bounds__(256) void d_kernel(
    const bf16* __restrict__ qp, const float* __restrict__ ks,
    float* __restrict__ D)
{
    int row  = blockIdx.x*8 + (threadIdx.x>>5);
    int lane = threadIdx.x&31;
    int b = row >> 12;
    uint4 u = *reinterpret_cast<const uint4*>(qp + (size_t)row*MF + lane*8);
    float4 k0 = *reinterpret_cast<const float4*>(ks + b*MF + lane*8);
    float4 k1 = *reinterpret_cast<const float4*>(ks + b*MF + lane*8 + 4);
    uint32_t a[4] = {u.x, u.y, u.z, u.w};
    float kk[8] = {k0.x,k0.y,k0.z,k0.w,k1.x,k1.y,k1.z,k1.w};
    float s=0.f;
    #pragma unroll
    for (int j=0;j<4;j++){
        float2 f = __bfloat1622float2(*reinterpret_cast<bf162*>(&a[j]));
        s += f.x*kk[2*j] + f.y*kk[2*j+1];
    }
    #pragma unroll
    for (int o=16;o>0;o>>=1) s += __shfl_xor_sync(0xffffffffu, s, o);
    if (lane==0) D[row]=s;
}

// ---------------- launch ---------------------------------------------------
extern "C" void kernel_launch(void* const* d_in, const int* in_sizes, int n_in,
                              void* d_out, int out_size)
{
    const float* x     = (const float*)d_in[0];
    const float* qw    = (const float*)d_in[1];
    const float* qb    = (const float*)d_in[2];
    const float* kw    = (const float*)d_in[3];
    const float* kb    = (const float*)d_in[4];
    const float* vw    = (const float*)d_in[5];
    const float* vb    = (const float*)d_in[6];
    const float* pw    = (const float*)d_in[7];
    const float* pb    = (const float*)d_in[8];
    const float* gamma = (const float*)d_in[9];
    const float* beta  = (const float*)d_in[10];
    const float* w     = (const float*)d_in[11];
    float* out = (float*)d_out;

    bf16 *xhl,*qk,*qkp,*G,*vtb,*kptb,*kptvb,*qkw,*pwb,*wb,*vw1536;
    float *v,*xd2,*D,*ks,*kptvp,*qkb;
    cudaGetSymbolAddress((void**)&xhl,   g_xhl);
    cudaGetSymbolAddress((void**)&qk,    g_qk);
    cudaGetSymbolAddress((void**)&qkp,   g_qkp);
    cudaGetSymbolAddress((void**)&G,     g_G);
    cudaGetSymbolAddress((void**)&vtb,   g_vtb);
    cudaGetSymbolAddress((void**)&kptb,  g_kptb);
    cudaGetSymbolAddress((void**)&kptvb, g_kptvb);
    cudaGetSymbolAddress((void**)&qkw,   g_qkw);
    cudaGetSymbolAddress((void**)&pwb,   g_pwb);
    cudaGetSymbolAddress((void**)&wb,    g_wb);
    cudaGetSymbolAddress((void**)&vw1536,g_vw1536);
    cudaGetSymbolAddress((void**)&v,     g_v);
    cudaGetSymbolAddress((void**)&xd2,   g_xd2);
    cudaGetSymbolAddress((void**)&D,     g_D);
    cudaGetSymbolAddress((void**)&ks,    g_ks);
    cudaGetSymbolAddress((void**)&kptvp, g_kptvp);
    cudaGetSymbolAddress((void**)&qkb,   g_qkb);

    cudaFuncSetAttribute(gemm_bf<0>, cudaFuncAttributeMaxDynamicSharedMemorySize, SMEM_B);
    cudaFuncSetAttribute(gemm_bf<1>, cudaFuncAttributeMaxDynamicSharedMemorySize, SMEM_B);
    cudaFuncSetAttribute(gemm_bf<4>, cudaFuncAttributeMaxDynamicSharedMemorySize, SMEM_B);
    cudaFuncSetAttribute(gemm_bf<5>, cudaFuncAttributeMaxDynamicSharedMemorySize, SMEM_B);
    cudaFuncSetAttribute(gemm_bf<6>, cudaFuncAttributeMaxDynamicSharedMemorySize, SMEM_B);
    cudaFuncSetAttribute(gemm_bf<7>, cudaFuncAttributeMaxDynamicSharedMemorySize, SMEM_B);

    dim3 blk(256);
    dim3 gblk(128);

    // 1) weight conversions (single launch)
    {
        int total = 4*N1 + MF*EE + 2*EE;
        conv_all<<<(total+255)/256,blk>>>(qw, kw, pw, w, vw, qb, kb,
                                          qkw, pwb, wb, vw1536, qkb);
    }

    // 2) LayerNorm -> xhl = [hi|lo|hi], row stride 1536
    ln_kernel<<<NR,128>>>(x, gamma, beta, xhl);

    // 3) q+k projections in one z-stacked launch (bf16 out)
    gemm_bf<0><<<dim3(NR/128, EE/128, 2),gblk,SMEM_B>>>(
        xhl, qkw, qk, EE, 3*EE, EE, EE, qkb, nullptr, nullptr, nullptr,
        0, (size_t)N1, (size_t)NR*EE, EE, 1);

    // 4) v in ONE fused K=1536 GEMM: xnh@vwh + xnl@vwh + xnh@vwl + vb (f32)
    gemm_bf<6><<<dim3(NR/128, EE/128, 1),gblk,SMEM_B>>>(
        xhl, vw1536, v, 3*EE, 3*EE, 3*EE, EE, vb, nullptr, nullptr, nullptr,
        0, 0, 0, 0, 1);

    // 5) row half-norms from bf16 q,k (stacked)
    xd_kernel<<<NR/8,256>>>(qk, qk + (size_t)NR*EE, xd2, xd2 + NR);

    // 6) features in one z-stacked launch (exp epilogue, bf16 out)
    gemm_bf<1><<<dim3(NR/128, MF/128, 2),gblk,SMEM_B>>>(
        qk, wb, qkp, EE, EE, EE, MF, nullptr, xd2, nullptr, nullptr,
        (size_t)NR*EE, 0, (size_t)NR*MF, NR, 1);

    // 7) ksum[b,m] from kp
    ksum_kernel<<<dim3(BB, MF/64),blk>>>(qkp + (size_t)NR*MF, ks);

    // 8) transposes: vtb[b][E][S] (f32->bf16), kptb[b][M][S] (bf16->bf16)
    transpose_t<float,bf16><<<dim3(EE/32, SS/32, BB),blk>>>(v, vtb, SS, EE);
    transpose_t<bf16,bf16> <<<dim3(MF/32, SS/32, BB),blk>>>(qkp + (size_t)NR*MF, kptb, SS, MF);

    // 9) kptv'[b][m][e] = sum_s kp[s,m]*v[s,e]: split-K partials, reduce -> bf16
    gemm_bf<4><<<dim3(MF/128, EE/128, BB*SPLITK),gblk,SMEM_B>>>(
        kptb, vtb, kptvp, SS/SPLITK, SS, SS, EE, nullptr, nullptr, nullptr, nullptr,
        (size_t)MF*SS, (size_t)EE*SS, (size_t)MF*EE, 0, SPLITK);
    reduce_kptv<<<dim3((EE*MF)/256, BB),blk>>>(kptvp, kptvb);

    // 10) D[r]
    d_kernel<<<NR/8,256>>>(qkp, ks, D);

    // 11) G[b][c][m] = sum_e pw[c,e]*kptv'[m,e]  (tiny per-batch GEMM, bf16 out)
    gemm_bf<5><<<dim3(EE/128, MF/128, BB),gblk,SMEM_B>>>(
        pwb, kptvb, G, EE, EE, EE, MF, nullptr, nullptr, nullptr, nullptr,
        0, (size_t)MF*EE, (size_t)EE*MF, 0, 1);

    // 12) out[s,c] = v + pb + (qp @ G^T)/(D+eps)   (K=256, f32 out)
    gemm_bf<7><<<dim3(SS/128, EE/128, BB),gblk,SMEM_B>>>(
        qkp, G, out, MF, MF, MF, EE, pb, nullptr, D, v,
        (size_t)SS*MF, (size_t)EE*MF, (size_t)SS*EE, SS, 1);
}